// round 1
// baseline (speedup 1.0000x reference)
#include <cuda_runtime.h>
#include <math.h>

#define B_  2
#define S_  512
#define N_  20000
#define D_  384
#define H_  3
#define C_  128
#define F_  384        // H*C
#define E_  320000
#define DG_ 128
#define BN_ (B_*N_)    // 40000
#define BE_ (B_*E_)    // 640000
#define NSPLIT 25
#define KCH 800        // 20000 / 25, = 50 * 16 exactly

// ---------------- device scratch (static, no allocation) ----------------
__device__ float g_Y[B_*S_*F_];       // x_enc @ Wlin^T          [2,512,384]
__device__ float g_uvw[3*F_];         // u, v, w vectors
__device__ float g_xp[BN_*F_];        // GAT-transformed features [40000,384]
__device__ float g_asrc[BN_*H_];
__device__ float g_adst[BN_*H_];
__device__ float g_max[BN_*H_];
__device__ float g_rden[BN_*H_];      // 1/denominator
__device__ int   g_off[BN_+1];        // CSR offsets (by dst)
__device__ int   g_cnt[BN_];
__device__ int   g_cur[BN_];
__device__ int   g_esrc[BE_];
__device__ int   g_edst[BE_];
__device__ float g_alpha[BE_*H_];
__device__ float g_gat[BN_*F_];       // GAT output (+bias_gat)
__device__ float g_tmp[B_*S_*F_];     // projection accumulator

__device__ __forceinline__ float lrelu(float x){ return x > 0.f ? x : 0.2f*x; }

// ---------------- tiny setup kernels ----------------
__global__ void k_zero(){
    int i = blockIdx.x*blockDim.x + threadIdx.x;
    if (i < BN_){ g_cnt[i] = 0; g_cur[i] = 0; }
}

__global__ void k_uvw(const float* __restrict__ Wlin,
                      const float* __restrict__ Wm,
                      const float* __restrict__ bm){
    int f = blockIdx.x*blockDim.x + threadIdx.x;
    if (f >= F_) return;
    float u = 0.f, v = 0.f, w = 0.f;
    for (int d = 0; d < D_; d++){
        float wl = Wlin[f*D_ + d];
        u += wl * Wm[d];
        v += wl * bm[d];
        w += wl;
    }
    g_uvw[f] = u; g_uvw[F_+f] = v; g_uvw[2*F_+f] = w;
}

__global__ void k_tmpinit(const float* __restrict__ bproj){
    int i = blockIdx.x*blockDim.x + threadIdx.x;
    if (i >= B_*S_*F_) return;
    int s = (i / F_) % S_;
    g_tmp[i] = bproj[s];
}

// ---------------- generic tiled GEMM, C = A @ Bm^T (+bias_col) ----------------
// A: [M,K] row-major (batched via strideA), Bm: [Ncol,K] row-major.
// Grids are exact: M % 64 == 0, Ncol % 64 == 0, K % 16 == 0.
__global__ void k_gemm_bt(const float* __restrict__ A, int strideA,
                          const float* __restrict__ Bm,
                          float* __restrict__ C, int strideC,
                          int K, int Ncol,
                          const float* __restrict__ bias_col){
    const float* Ab = A + blockIdx.z * strideA;
    float* Cb = C + blockIdx.z * strideC;
    int m0 = blockIdx.y*64, n0 = blockIdx.x*64;
    __shared__ float As[16][64];
    __shared__ float Bs[16][64];
    int tid  = threadIdx.x;
    int tm   = tid >> 4, tn = tid & 15;
    int lrow = tid >> 2;          // 0..63
    int lcol = (tid & 3) * 4;     // 0,4,8,12
    float acc[4][4] = {};
    for (int k0 = 0; k0 < K; k0 += 16){
        float4 av = *(const float4*)(Ab + (m0 + lrow)*K + k0 + lcol);
        As[lcol+0][lrow]=av.x; As[lcol+1][lrow]=av.y; As[lcol+2][lrow]=av.z; As[lcol+3][lrow]=av.w;
        float4 bv = *(const float4*)(Bm + (n0 + lrow)*K + k0 + lcol);
        Bs[lcol+0][lrow]=bv.x; Bs[lcol+1][lrow]=bv.y; Bs[lcol+2][lrow]=bv.z; Bs[lcol+3][lrow]=bv.w;
        __syncthreads();
        #pragma unroll
        for (int kk = 0; kk < 16; kk++){
            float4 a4 = *(const float4*)&As[kk][tm*4];
            float4 b4 = *(const float4*)&Bs[kk][tn*4];
            float ar[4] = {a4.x,a4.y,a4.z,a4.w};
            float br[4] = {b4.x,b4.y,b4.z,b4.w};
            #pragma unroll
            for (int i = 0; i < 4; i++)
                #pragma unroll
                for (int j = 0; j < 4; j++)
                    acc[i][j] = fmaf(ar[i], br[j], acc[i][j]);
        }
        __syncthreads();
    }
    #pragma unroll
    for (int i = 0; i < 4; i++){
        int row = m0 + tm*4 + i;
        #pragma unroll
        for (int j = 0; j < 4; j++){
            int col = n0 + tn*4 + j;
            float v = acc[i][j];
            if (bias_col) v += bias_col[col];
            Cb[row*Ncol + col] = v;
        }
    }
}

// ---------------- xp = Wq @ Y_b + bq*w + mask*u + v ----------------
// A = Wq [20000,512], B = Y_b [512,384] row-major ([K,N] layout).
__global__ void k_xp(const float* __restrict__ Wq,
                     const float* __restrict__ bq,
                     const float* __restrict__ mask){
    int bz = blockIdx.z;
    const float* Bm = g_Y + bz*(S_*F_);
    int m0 = blockIdx.y*64, n0 = blockIdx.x*64;
    __shared__ float As[16][64];
    __shared__ float Bs[16][64];
    int tid = threadIdx.x;
    int tm = tid >> 4, tn = tid & 15;
    int arow = tid >> 2, acol = (tid & 3) * 4;
    int brow = tid >> 4, bcol = (tid & 15) * 4;
    float acc[4][4] = {};
    for (int k0 = 0; k0 < S_; k0 += 16){
        int gr = m0 + arow;
        float4 av = (gr < N_) ? *(const float4*)(Wq + gr*S_ + k0 + acol)
                              : make_float4(0.f,0.f,0.f,0.f);
        As[acol+0][arow]=av.x; As[acol+1][arow]=av.y; As[acol+2][arow]=av.z; As[acol+3][arow]=av.w;
        float4 bv = *(const float4*)(Bm + (k0 + brow)*F_ + n0 + bcol);
        *(float4*)&Bs[brow][bcol] = bv;
        __syncthreads();
        #pragma unroll
        for (int kk = 0; kk < 16; kk++){
            float4 a4 = *(const float4*)&As[kk][tm*4];
            float4 b4 = *(const float4*)&Bs[kk][tn*4];
            float ar[4] = {a4.x,a4.y,a4.z,a4.w};
            float br[4] = {b4.x,b4.y,b4.z,b4.w};
            #pragma unroll
            for (int i = 0; i < 4; i++)
                #pragma unroll
                for (int j = 0; j < 4; j++)
                    acc[i][j] = fmaf(ar[i], br[j], acc[i][j]);
        }
        __syncthreads();
    }
    #pragma unroll
    for (int i = 0; i < 4; i++){
        int row = m0 + tm*4 + i;
        if (row >= N_) continue;
        float bqv = bq[row];
        float mv  = mask[bz*N_ + row];
        #pragma unroll
        for (int j = 0; j < 4; j++){
            int col = n0 + tn*4 + j;
            g_xp[(bz*N_ + row)*F_ + col] =
                acc[i][j] + bqv*g_uvw[2*F_+col] + mv*g_uvw[col] + g_uvw[F_+col];
        }
    }
}

// ---------------- projection: tmp[b,s,f] += sum_n Wproj[s,n]*gat[b,n,f] (split-K) ----------------
__global__ void k_proj(const float* __restrict__ Wproj){
    int z  = blockIdx.z;
    int bz = z / NSPLIT, sp = z % NSPLIT;
    int kbeg = sp * KCH;
    const float* Bm = g_gat + bz*(N_*F_);
    int m0 = blockIdx.y*64, n0 = blockIdx.x*64;
    __shared__ float As[16][64];
    __shared__ float Bs[16][64];
    int tid = threadIdx.x;
    int tm = tid >> 4, tn = tid & 15;
    int arow = tid >> 2, acol = (tid & 3) * 4;
    int brow = tid >> 4, bcol = (tid & 15) * 4;
    float acc[4][4] = {};
    for (int k0 = kbeg; k0 < kbeg + KCH; k0 += 16){
        float4 av = *(const float4*)(Wproj + (m0 + arow)*N_ + k0 + acol);
        As[acol+0][arow]=av.x; As[acol+1][arow]=av.y; As[acol+2][arow]=av.z; As[acol+3][arow]=av.w;
        float4 bv = *(const float4*)(Bm + (k0 + brow)*F_ + n0 + bcol);
        *(float4*)&Bs[brow][bcol] = bv;
        __syncthreads();
        #pragma unroll
        for (int kk = 0; kk < 16; kk++){
            float4 a4 = *(const float4*)&As[kk][tm*4];
            float4 b4 = *(const float4*)&Bs[kk][tn*4];
            float ar[4] = {a4.x,a4.y,a4.z,a4.w};
            float br[4] = {b4.x,b4.y,b4.z,b4.w};
            #pragma unroll
            for (int i = 0; i < 4; i++)
                #pragma unroll
                for (int j = 0; j < 4; j++)
                    acc[i][j] = fmaf(ar[i], br[j], acc[i][j]);
        }
        __syncthreads();
    }
    #pragma unroll
    for (int i = 0; i < 4; i++){
        int row = m0 + tm*4 + i;
        #pragma unroll
        for (int j = 0; j < 4; j++){
            int col = n0 + tn*4 + j;
            atomicAdd(&g_tmp[(bz*S_ + row)*F_ + col], acc[i][j]);
        }
    }
}

// ---------------- attention scalars: a_src / a_dst ----------------
__global__ void k_attn(const float* __restrict__ att_src,
                       const float* __restrict__ att_dst){
    int gw = (blockIdx.x*blockDim.x + threadIdx.x) >> 5;
    if (gw >= BN_*H_) return;
    int lane = threadIdx.x & 31;
    int n = gw / H_, h = gw % H_;
    const float* xrow = g_xp + n*F_ + h*C_;
    float s1 = 0.f, s2 = 0.f;
    #pragma unroll
    for (int k = 0; k < 4; k++){
        int c = lane + k*32;
        float xv = xrow[c];
        s1 = fmaf(xv, att_src[h*C_ + c], s1);
        s2 = fmaf(xv, att_dst[h*C_ + c], s2);
    }
    #pragma unroll
    for (int o = 16; o; o >>= 1){
        s1 += __shfl_xor_sync(0xffffffffu, s1, o);
        s2 += __shfl_xor_sync(0xffffffffu, s2, o);
    }
    if (lane == 0){ g_asrc[n*H_+h] = s1; g_adst[n*H_+h] = s2; }
}

// ---------------- CSR build ----------------
__global__ void k_count(const int* __restrict__ ei){
    int e = blockIdx.x*blockDim.x + threadIdx.x;
    if (e >= BE_) return;
    int b = e / E_, j = e - b*E_;
    int dst = ei[E_ + j] + b*N_;
    atomicAdd(&g_cnt[dst], 1);
}

__global__ void k_scan(){
    __shared__ int ssum[1024];
    int tid = threadIdx.x;
    const int CH = (BN_ + 1023) / 1024;   // 40
    int base = tid * CH;
    int s = 0;
    for (int i = 0; i < CH; i++){
        int idx = base + i;
        if (idx < BN_) s += g_cnt[idx];
    }
    ssum[tid] = s;
    __syncthreads();
    for (int off = 1; off < 1024; off <<= 1){
        int v = (tid >= off) ? ssum[tid - off] : 0;
        __syncthreads();
        ssum[tid] += v;
        __syncthreads();
    }
    int run = ssum[tid] - s;   // exclusive
    for (int i = 0; i < CH; i++){
        int idx = base + i;
        if (idx < BN_){ g_off[idx] = run; run += g_cnt[idx]; }
    }
    if (tid == 1023) g_off[BN_] = ssum[1023];
}

__global__ void k_scatter(const int* __restrict__ ei){
    int e = blockIdx.x*blockDim.x + threadIdx.x;
    if (e >= BE_) return;
    int b = e / E_, j = e - b*E_;
    int src = ei[j]       + b*N_;
    int dst = ei[E_ + j]  + b*N_;
    int pos = g_off[dst] + atomicAdd(&g_cur[dst], 1);
    g_esrc[pos] = src;
    g_edst[pos] = dst;
}

// ---------------- per-node segment softmax stats (max, 1/denom) ----------------
__global__ void k_softmax(){
    int gw = (blockIdx.x*blockDim.x + threadIdx.x) >> 5;
    if (gw >= BN_) return;
    int lane = threadIdx.x & 31;
    int n = gw;
    float ad0 = g_adst[n*3+0], ad1 = g_adst[n*3+1], ad2 = g_adst[n*3+2];
    float e0s = lrelu(g_asrc[n*3+0] + ad0);
    float e1s = lrelu(g_asrc[n*3+1] + ad1);
    float e2s = lrelu(g_asrc[n*3+2] + ad2);
    float m0 = e0s, m1 = e1s, m2 = e2s;
    int beg = g_off[n], end = g_off[n+1];
    for (int i = beg + lane; i < end; i += 32){
        int s = g_esrc[i];
        m0 = fmaxf(m0, lrelu(g_asrc[s*3+0] + ad0));
        m1 = fmaxf(m1, lrelu(g_asrc[s*3+1] + ad1));
        m2 = fmaxf(m2, lrelu(g_asrc[s*3+2] + ad2));
    }
    #pragma unroll
    for (int o = 16; o; o >>= 1){
        m0 = fmaxf(m0, __shfl_xor_sync(0xffffffffu, m0, o));
        m1 = fmaxf(m1, __shfl_xor_sync(0xffffffffu, m1, o));
        m2 = fmaxf(m2, __shfl_xor_sync(0xffffffffu, m2, o));
    }
    float s0 = 0.f, s1 = 0.f, s2 = 0.f;
    for (int i = beg + lane; i < end; i += 32){
        int s = g_esrc[i];
        s0 += __expf(lrelu(g_asrc[s*3+0] + ad0) - m0);
        s1 += __expf(lrelu(g_asrc[s*3+1] + ad1) - m1);
        s2 += __expf(lrelu(g_asrc[s*3+2] + ad2) - m2);
    }
    #pragma unroll
    for (int o = 16; o; o >>= 1){
        s0 += __shfl_xor_sync(0xffffffffu, s0, o);
        s1 += __shfl_xor_sync(0xffffffffu, s1, o);
        s2 += __shfl_xor_sync(0xffffffffu, s2, o);
    }
    if (lane == 0){
        s0 += __expf(e0s - m0);
        s1 += __expf(e1s - m1);
        s2 += __expf(e2s - m2);
        g_max[n*3+0] = m0; g_max[n*3+1] = m1; g_max[n*3+2] = m2;
        g_rden[n*3+0] = 1.f/s0; g_rden[n*3+1] = 1.f/s1; g_rden[n*3+2] = 1.f/s2;
    }
}

// ---------------- per-edge alpha ----------------
__global__ void k_alpha(){
    int i = blockIdx.x*blockDim.x + threadIdx.x;
    if (i >= BE_) return;
    int s = g_esrc[i], d = g_edst[i];
    #pragma unroll
    for (int h = 0; h < 3; h++){
        float e = lrelu(g_asrc[s*3+h] + g_adst[d*3+h]);
        g_alpha[i*3+h] = __expf(e - g_max[d*3+h]) * g_rden[d*3+h];
    }
}

// ---------------- aggregation: one block (96 threads) per dst node ----------------
__global__ void k_aggregate(const float* __restrict__ bias_gat){
    int n = blockIdx.x;
    int tid = threadIdx.x;       // 0..95, thread covers features [tid*4, tid*4+4)
    int h = tid >> 5;            // head = (tid*4)/128
    int beg = g_off[n], end = g_off[n+1];
    const float4* xp4 = (const float4*)g_xp;
    float4 acc = make_float4(0.f, 0.f, 0.f, 0.f);
    for (int i = beg; i < end; i++){
        int s = g_esrc[i];
        float al = g_alpha[i*3 + h];
        float4 v = xp4[s*96 + tid];
        acc.x = fmaf(v.x, al, acc.x);
        acc.y = fmaf(v.y, al, acc.y);
        acc.z = fmaf(v.z, al, acc.z);
        acc.w = fmaf(v.w, al, acc.w);
    }
    // self-loop
    float es  = lrelu(g_asrc[n*3+h] + g_adst[n*3+h]);
    float als = __expf(es - g_max[n*3+h]) * g_rden[n*3+h];
    float4 v = xp4[n*96 + tid];
    acc.x = fmaf(v.x, als, acc.x);
    acc.y = fmaf(v.y, als, acc.y);
    acc.z = fmaf(v.z, als, acc.z);
    acc.w = fmaf(v.w, als, acc.w);
    float4 bg = ((const float4*)bias_gat)[tid];
    acc.x += bg.x; acc.y += bg.y; acc.z += bg.z; acc.w += bg.w;
    ((float4*)g_gat)[n*96 + tid] = acc;
}

// ---------------- host launch ----------------
extern "C" void kernel_launch(void* const* d_in, const int* in_sizes, int n_in,
                              void* d_out, int out_size){
    const float* x_enc    = (const float*)d_in[0];
    const float* mask     = (const float*)d_in[1];
    const int*   ei       = (const int*)  d_in[2];
    const float* Wq       = (const float*)d_in[3];
    const float* bq       = (const float*)d_in[4];
    const float* Wm       = (const float*)d_in[5];
    const float* bm       = (const float*)d_in[6];
    const float* Wlin     = (const float*)d_in[7];
    const float* att_src  = (const float*)d_in[8];
    const float* att_dst  = (const float*)d_in[9];
    const float* bias_gat = (const float*)d_in[10];
    const float* Wproj    = (const float*)d_in[11];
    const float* bproj    = (const float*)d_in[12];
    const float* Wtemp    = (const float*)d_in[13];
    const float* btemp    = (const float*)d_in[14];
    float* out = (float*)d_out;

    void *pY = nullptr, *pTmp = nullptr;
    cudaGetSymbolAddress(&pY,   g_Y);
    cudaGetSymbolAddress(&pTmp, g_tmp);

    // setup
    k_zero<<<(BN_ + 255)/256, 256>>>();
    k_uvw<<<3, 128>>>(Wlin, Wm, bm);

    // Y_b = x_enc[b] @ Wlin^T    [2,512,384]
    k_gemm_bt<<<dim3(F_/64, S_/64, B_), 256>>>(
        x_enc, S_*D_, Wlin, (float*)pY, S_*F_, D_, F_, nullptr);

    // CSR build (independent of GEMMs, same stream)
    k_count<<<(BE_ + 255)/256, 256>>>(ei);
    k_scan<<<1, 1024>>>();
    k_scatter<<<(BE_ + 255)/256, 256>>>(ei);

    // xp = Wq @ Y_b + bq*w + mask*u + v   [40000,384]
    k_xp<<<dim3(F_/64, (N_ + 63)/64, B_), 256>>>(Wq, bq, mask);

    // attention scalars, softmax stats, per-edge alpha
    k_attn<<<(BN_*H_*32 + 127)/128, 128>>>(att_src, att_dst);
    k_softmax<<<(BN_*32 + 127)/128, 128>>>();
    k_alpha<<<(BE_ + 255)/256, 256>>>();

    // GAT aggregation (+bias_gat)
    k_aggregate<<<BN_, 96>>>(bias_gat);

    // projection with bproj init + split-K atomics
    k_tmpinit<<<(B_*S_*F_ + 255)/256, 256>>>(bproj);
    k_proj<<<dim3(F_/64, S_/64, B_*NSPLIT), 256>>>(Wproj);

    // final: out = tmp @ Wtemp^T + btemp    [2*512,128]
    k_gemm_bt<<<dim3(DG_/64, (B_*S_)/64, 1), 256>>>(
        (const float*)pTmp, 0, Wtemp, out, 0, F_, DG_, btemp);
}

// round 2
// speedup vs baseline: 1.7822x; 1.7822x over previous
#include <cuda_runtime.h>
#include <cuda_bf16.h>
#include <math.h>

#define B_  2
#define S_  512
#define N_  20000
#define D_  384
#define H_  3
#define C_  128
#define F_  384        // H*C
#define E_  320000
#define DG_ 128
#define BN_ (B_*N_)    // 40000
#define BE_ (B_*E_)    // 640000

#define K3_XP   1536          // 3*512
#define K3_PJ   60000         // 3*20000
#define NSPLIT  25
#define KCHUNK  2400          // 60000/25, 75 iters of 32
#define NITER_PJ 75
#define NITER_XP 48

// ---------------- device scratch (static, no allocation) ----------------
__device__ float g_Y[B_*S_*F_];                       // x_enc @ Wlin^T  [2,512,384] fp32
__device__ __align__(16) __nv_bfloat16 g_Y3[B_*K3_XP*F_];     // hi;hi;lo  [2,1536,384]
__device__ __align__(16) __nv_bfloat16 g_Wq3[(size_t)N_*K3_XP];      // hi|lo|hi  [20000,1536]
__device__ __align__(16) __nv_bfloat16 g_Wp3[(size_t)S_*K3_PJ];      // hi|lo|hi  [512,60000]
__device__ __align__(16) __nv_bfloat16 g_gat3[(size_t)B_*K3_PJ*F_];  // hi;hi;lo  [2,60000,384]
__device__ float g_uvw[3*F_];
__device__ float g_xp[(size_t)BN_*F_];
__device__ float g_asrc[BN_*H_];
__device__ float g_adst[BN_*H_];
__device__ float g_max[BN_*H_];
__device__ float g_rden[BN_*H_];
__device__ int   g_off[BN_+1];
__device__ int   g_cnt[BN_];
__device__ int   g_cur[BN_];
__device__ int   g_esrc[BE_];
__device__ int   g_edst[BE_];
__device__ float g_alpha[(size_t)BE_*H_];
__device__ float g_tmp[B_*S_*F_];

__device__ __forceinline__ float lrelu(float x){ return x > 0.f ? x : 0.2f*x; }

// ---------------- PTX helpers ----------------
__device__ __forceinline__ unsigned su(const void* p){
    return (unsigned)__cvta_generic_to_shared(p);
}
__device__ __forceinline__ void cpa16(unsigned dst, const void* src, bool pred){
    int sz = pred ? 16 : 0;
    asm volatile("cp.async.cg.shared.global [%0], [%1], 16, %2;\n"
                 :: "r"(dst), "l"(src), "r"(sz));
}
__device__ __forceinline__ void cp_commit(){ asm volatile("cp.async.commit_group;\n"); }
__device__ __forceinline__ void cp_wait1(){ asm volatile("cp.async.wait_group 1;\n"); }
__device__ __forceinline__ void ldsm4(unsigned addr, unsigned &r0, unsigned &r1, unsigned &r2, unsigned &r3){
    asm volatile("ldmatrix.sync.aligned.m8n8.x4.shared.b16 {%0,%1,%2,%3}, [%4];\n"
                 : "=r"(r0),"=r"(r1),"=r"(r2),"=r"(r3) : "r"(addr));
}
__device__ __forceinline__ void ldsm4t(unsigned addr, unsigned &r0, unsigned &r1, unsigned &r2, unsigned &r3){
    asm volatile("ldmatrix.sync.aligned.m8n8.x4.trans.shared.b16 {%0,%1,%2,%3}, [%4];\n"
                 : "=r"(r0),"=r"(r1),"=r"(r2),"=r"(r3) : "r"(addr));
}
__device__ __forceinline__ void mma16816(float* c, const unsigned* a, const unsigned* b){
    asm volatile("mma.sync.aligned.m16n8k16.row.col.f32.bf16.bf16.f32 "
                 "{%0,%1,%2,%3},{%4,%5,%6,%7},{%8,%9},{%0,%1,%2,%3};\n"
                 : "+f"(c[0]),"+f"(c[1]),"+f"(c[2]),"+f"(c[3])
                 : "r"(a[0]),"r"(a[1]),"r"(a[2]),"r"(a[3]),"r"(b[0]),"r"(b[1]));
}

// ---------------- tiny setup kernels ----------------
__global__ void k_zero(){
    int i = blockIdx.x*blockDim.x + threadIdx.x;
    if (i < BN_){ g_cnt[i] = 0; g_cur[i] = 0; }
}

__global__ void k_uvw(const float* __restrict__ Wlin,
                      const float* __restrict__ Wm,
                      const float* __restrict__ bm){
    int f = blockIdx.x*blockDim.x + threadIdx.x;
    if (f >= F_) return;
    float u = 0.f, v = 0.f, w = 0.f;
    for (int d = 0; d < D_; d++){
        float wl = Wlin[f*D_ + d];
        u += wl * Wm[d];
        v += wl * bm[d];
        w += wl;
    }
    g_uvw[f] = u; g_uvw[F_+f] = v; g_uvw[2*F_+f] = w;
}

__global__ void k_tmpinit(const float* __restrict__ bproj){
    int i = blockIdx.x*blockDim.x + threadIdx.x;
    if (i >= B_*S_*F_) return;
    int s = (i / F_) % S_;
    g_tmp[i] = bproj[s];
}

// ---------------- hi/lo split conversions ----------------
__global__ void k_split_wq(const float* __restrict__ Wq){
    long i = (long)blockIdx.x*blockDim.x + threadIdx.x;
    if (i >= (long)N_*S_) return;
    int m = (int)(i / S_), k = (int)(i - (long)m*S_);
    float x = Wq[i];
    __nv_bfloat16 h = __float2bfloat16(x);
    __nv_bfloat16 l = __float2bfloat16(x - __bfloat162float(h));
    size_t base = (size_t)m*K3_XP;
    g_Wq3[base + k]        = h;
    g_Wq3[base + 512 + k]  = l;
    g_Wq3[base + 1024 + k] = h;
}

__global__ void k_split_wp(const float* __restrict__ Wproj){
    long i = (long)blockIdx.x*blockDim.x + threadIdx.x;
    if (i >= (long)S_*N_) return;
    int m = (int)(i / N_), k = (int)(i - (long)m*N_);
    float x = Wproj[i];
    __nv_bfloat16 h = __float2bfloat16(x);
    __nv_bfloat16 l = __float2bfloat16(x - __bfloat162float(h));
    size_t base = (size_t)m*K3_PJ;
    g_Wp3[base + k]          = h;
    g_Wp3[base + 20000 + k]  = l;
    g_Wp3[base + 40000 + k]  = h;
}

__global__ void k_split_Y(){
    int i = blockIdx.x*blockDim.x + threadIdx.x;
    if (i >= B_*S_*F_) return;
    int b = i / (S_*F_);
    int r = (i / F_) % S_;
    int n = i % F_;
    float x = g_Y[i];
    __nv_bfloat16 h = __float2bfloat16(x);
    __nv_bfloat16 l = __float2bfloat16(x - __bfloat162float(h));
    size_t base = (size_t)b*K3_XP*F_;
    g_Y3[base + (size_t)r*F_ + n]          = h;
    g_Y3[base + (size_t)(512 + r)*F_ + n]  = h;
    g_Y3[base + (size_t)(1024 + r)*F_ + n] = l;
}

// ---------------- fp32 tiled GEMM (small matrices only), C = A @ Bm^T (+bias_col) ----------------
__global__ void k_gemm_bt(const float* __restrict__ A, int strideA,
                          const float* __restrict__ Bm,
                          float* __restrict__ C, int strideC,
                          int K, int Ncol,
                          const float* __restrict__ bias_col){
    const float* Ab = A + blockIdx.z * strideA;
    float* Cb = C + blockIdx.z * strideC;
    int m0 = blockIdx.y*64, n0 = blockIdx.x*64;
    __shared__ float As[16][64];
    __shared__ float Bs[16][64];
    int tid  = threadIdx.x;
    int tm   = tid >> 4, tn = tid & 15;
    int lrow = tid >> 2;
    int lcol = (tid & 3) * 4;
    float acc[4][4] = {};
    for (int k0 = 0; k0 < K; k0 += 16){
        float4 av = *(const float4*)(Ab + (m0 + lrow)*K + k0 + lcol);
        As[lcol+0][lrow]=av.x; As[lcol+1][lrow]=av.y; As[lcol+2][lrow]=av.z; As[lcol+3][lrow]=av.w;
        float4 bv = *(const float4*)(Bm + (n0 + lrow)*K + k0 + lcol);
        Bs[lcol+0][lrow]=bv.x; Bs[lcol+1][lrow]=bv.y; Bs[lcol+2][lrow]=bv.z; Bs[lcol+3][lrow]=bv.w;
        __syncthreads();
        #pragma unroll
        for (int kk = 0; kk < 16; kk++){
            float4 a4 = *(const float4*)&As[kk][tm*4];
            float4 b4 = *(const float4*)&Bs[kk][tn*4];
            float ar[4] = {a4.x,a4.y,a4.z,a4.w};
            float br[4] = {b4.x,b4.y,b4.z,b4.w};
            #pragma unroll
            for (int i = 0; i < 4; i++)
                #pragma unroll
                for (int j = 0; j < 4; j++)
                    acc[i][j] = fmaf(ar[i], br[j], acc[i][j]);
        }
        __syncthreads();
    }
    #pragma unroll
    for (int i = 0; i < 4; i++){
        int row = m0 + tm*4 + i;
        #pragma unroll
        for (int j = 0; j < 4; j++){
            int col = n0 + tn*4 + j;
            float v = acc[i][j];
            if (bias_col) v += bias_col[col];
            Cb[row*Ncol + col] = v;
        }
    }
}

// ---------------- bf16 tensor-core GEMM, 128x128x32 tiles, 2-stage cp.async ----------------
// C[M,384] (+= / =) A[M,lda] @ B[K3,384],  bf16 operands, fp32 accumulate.
// ATOMIC=false: xp epilogue (fused bq*w + mask*u + v, direct store)
// ATOMIC=true : split-K atomicAdd epilogue
template<bool ATOMIC>
__global__ __launch_bounds__(256, 2)
void k_mma(const __nv_bfloat16* __restrict__ A, int lda, int M,
           const __nv_bfloat16* __restrict__ Bbase, size_t strideB,
           float* __restrict__ Cbase, int strideC,
           int nsplit, int kchunk, int niter,
           const float* __restrict__ bq, const float* __restrict__ mask)
{
    __shared__ __align__(16) __nv_bfloat16 sA[2][128][40];
    __shared__ __align__(16) __nv_bfloat16 sB[2][32][136];

    int bz = blockIdx.z / nsplit, sp = blockIdx.z % nsplit;
    int kbeg = sp * kchunk;
    int m0 = blockIdx.y * 128, n0 = blockIdx.x * 128;
    const __nv_bfloat16* Bp = Bbase + (size_t)bz * strideB;
    float* C = Cbase + (size_t)bz * strideC;

    int tid = threadIdx.x, lane = tid & 31, wid = tid >> 5;
    int wm = wid & 3, wn = wid >> 2;      // 4 x 2 warp grid, warp tile 32m x 64n

    auto load_stage = [&](int st, int kpos){
        #pragma unroll
        for (int c = tid; c < 512; c += 256){       // A tile: 128 x 32
            int row = c >> 2, seg = c & 3;
            int gr = m0 + row;
            const void* src = A + (size_t)(gr < M ? gr : M-1) * lda + kpos + seg*8;
            cpa16(su(&sA[st][row][seg*8]), src, gr < M);
        }
        #pragma unroll
        for (int c = tid; c < 512; c += 256){       // B tile: 32 x 128
            int row = c >> 4, seg = c & 15;
            const void* src = Bp + (size_t)(kpos + row) * F_ + n0 + seg*8;
            cpa16(su(&sB[st][row][seg*8]), src, true);
        }
    };

    float acc[2][8][4] = {};

    load_stage(0, kbeg);
    cp_commit();

    for (int it = 0; it < niter; ++it){
        if (it + 1 < niter) load_stage((it+1)&1, kbeg + (it+1)*32);
        cp_commit();
        cp_wait1();
        __syncthreads();
        int st = it & 1;
        int lrow = lane & 15, lhi = lane >> 4;
        #pragma unroll
        for (int kk = 0; kk < 2; ++kk){
            int k0 = kk*16;
            unsigned a[2][4], b[8][2];
            #pragma unroll
            for (int mi = 0; mi < 2; ++mi){
                unsigned addr = su(&sA[st][wm*32 + mi*16 + lrow][k0 + lhi*8]);
                ldsm4(addr, a[mi][0], a[mi][1], a[mi][2], a[mi][3]);
            }
            #pragma unroll
            for (int nt = 0; nt < 4; ++nt){
                unsigned addr = su(&sB[st][k0 + lrow][wn*64 + nt*16 + lhi*8]);
                unsigned r0,r1,r2,r3;
                ldsm4t(addr, r0,r1,r2,r3);
                b[nt*2  ][0]=r0; b[nt*2  ][1]=r1;
                b[nt*2+1][0]=r2; b[nt*2+1][1]=r3;
            }
            #pragma unroll
            for (int mi = 0; mi < 2; ++mi)
                #pragma unroll
                for (int ni = 0; ni < 8; ++ni)
                    mma16816(acc[mi][ni], a[mi], b[ni]);
        }
        __syncthreads();
    }

    // epilogue
    int g = lane >> 2, tig = lane & 3;
    #pragma unroll
    for (int mi = 0; mi < 2; ++mi){
        #pragma unroll
        for (int half = 0; half < 2; ++half){
            int row = m0 + wm*32 + mi*16 + g + half*8;
            if (row >= M) continue;
            float bqv = 0.f, mv = 0.f;
            if constexpr (!ATOMIC){
                bqv = bq[row];
                mv  = mask[bz*N_ + row];
            }
            #pragma unroll
            for (int ni = 0; ni < 8; ++ni){
                int col = n0 + wn*64 + ni*8 + tig*2;
                float v0 = acc[mi][ni][half*2+0];
                float v1 = acc[mi][ni][half*2+1];
                if constexpr (ATOMIC){
                    atomicAdd(&C[(size_t)row*F_ + col],     v0);
                    atomicAdd(&C[(size_t)row*F_ + col + 1], v1);
                } else {
                    v0 += bqv*g_uvw[2*F_+col]   + mv*g_uvw[col]   + g_uvw[F_+col];
                    v1 += bqv*g_uvw[2*F_+col+1] + mv*g_uvw[col+1] + g_uvw[F_+col+1];
                    *(float2*)&C[(size_t)row*F_ + col] = make_float2(v0, v1);
                }
            }
        }
    }
}

// ---------------- attention scalars ----------------
__global__ void k_attn(const float* __restrict__ att_src,
                       const float* __restrict__ att_dst){
    int gw = (blockIdx.x*blockDim.x + threadIdx.x) >> 5;
    if (gw >= BN_*H_) return;
    int lane = threadIdx.x & 31;
    int n = gw / H_, h = gw % H_;
    const float* xrow = g_xp + (size_t)n*F_ + h*C_;
    float s1 = 0.f, s2 = 0.f;
    #pragma unroll
    for (int k = 0; k < 4; k++){
        int c = lane + k*32;
        float xv = xrow[c];
        s1 = fmaf(xv, att_src[h*C_ + c], s1);
        s2 = fmaf(xv, att_dst[h*C_ + c], s2);
    }
    #pragma unroll
    for (int o = 16; o; o >>= 1){
        s1 += __shfl_xor_sync(0xffffffffu, s1, o);
        s2 += __shfl_xor_sync(0xffffffffu, s2, o);
    }
    if (lane == 0){ g_asrc[n*H_+h] = s1; g_adst[n*H_+h] = s2; }
}

// ---------------- CSR build ----------------
__global__ void k_count(const int* __restrict__ ei){
    int e = blockIdx.x*blockDim.x + threadIdx.x;
    if (e >= BE_) return;
    int b = e / E_, j = e - b*E_;
    int dst = ei[E_ + j] + b*N_;
    atomicAdd(&g_cnt[dst], 1);
}

__global__ void k_scan(){
    __shared__ int ssum[1024];
    int tid = threadIdx.x;
    const int CH = (BN_ + 1023) / 1024;
    int base = tid * CH;
    int s = 0;
    for (int i = 0; i < CH; i++){
        int idx = base + i;
        if (idx < BN_) s += g_cnt[idx];
    }
    ssum[tid] = s;
    __syncthreads();
    for (int off = 1; off < 1024; off <<= 1){
        int v = (tid >= off) ? ssum[tid - off] : 0;
        __syncthreads();
        ssum[tid] += v;
        __syncthreads();
    }
    int run = ssum[tid] - s;
    for (int i = 0; i < CH; i++){
        int idx = base + i;
        if (idx < BN_){ g_off[idx] = run; run += g_cnt[idx]; }
    }
    if (tid == 1023) g_off[BN_] = ssum[1023];
}

__global__ void k_scatter(const int* __restrict__ ei){
    int e = blockIdx.x*blockDim.x + threadIdx.x;
    if (e >= BE_) return;
    int b = e / E_, j = e - b*E_;
    int src = ei[j]       + b*N_;
    int dst = ei[E_ + j]  + b*N_;
    int pos = g_off[dst] + atomicAdd(&g_cur[dst], 1);
    g_esrc[pos] = src;
    g_edst[pos] = dst;
}

// ---------------- per-node segment softmax stats ----------------
__global__ void k_softmax(){
    int gw = (blockIdx.x*blockDim.x + threadIdx.x) >> 5;
    if (gw >= BN_) return;
    int lane = threadIdx.x & 31;
    int n = gw;
    float ad0 = g_adst[n*3+0], ad1 = g_adst[n*3+1], ad2 = g_adst[n*3+2];
    float e0s = lrelu(g_asrc[n*3+0] + ad0);
    float e1s = lrelu(g_asrc[n*3+1] + ad1);
    float e2s = lrelu(g_asrc[n*3+2] + ad2);
    float m0 = e0s, m1 = e1s, m2 = e2s;
    int beg = g_off[n], end = g_off[n+1];
    for (int i = beg + lane; i < end; i += 32){
        int s = g_esrc[i];
        m0 = fmaxf(m0, lrelu(g_asrc[s*3+0] + ad0));
        m1 = fmaxf(m1, lrelu(g_asrc[s*3+1] + ad1));
        m2 = fmaxf(m2, lrelu(g_asrc[s*3+2] + ad2));
    }
    #pragma unroll
    for (int o = 16; o; o >>= 1){
        m0 = fmaxf(m0, __shfl_xor_sync(0xffffffffu, m0, o));
        m1 = fmaxf(m1, __shfl_xor_sync(0xffffffffu, m1, o));
        m2 = fmaxf(m2, __shfl_xor_sync(0xffffffffu, m2, o));
    }
    float s0 = 0.f, s1 = 0.f, s2 = 0.f;
    for (int i = beg + lane; i < end; i += 32){
        int s = g_esrc[i];
        s0 += __expf(lrelu(g_asrc[s*3+0] + ad0) - m0);
        s1 += __expf(lrelu(g_asrc[s*3+1] + ad1) - m1);
        s2 += __expf(lrelu(g_asrc[s*3+2] + ad2) - m2);
    }
    #pragma unroll
    for (int o = 16; o; o >>= 1){
        s0 += __shfl_xor_sync(0xffffffffu, s0, o);
        s1 += __shfl_xor_sync(0xffffffffu, s1, o);
        s2 += __shfl_xor_sync(0xffffffffu, s2, o);
    }
    if (lane == 0){
        s0 += __expf(e0s - m0);
        s1 += __expf(e1s - m1);
        s2 += __expf(e2s - m2);
        g_max[n*3+0] = m0; g_max[n*3+1] = m1; g_max[n*3+2] = m2;
        g_rden[n*3+0] = 1.f/s0; g_rden[n*3+1] = 1.f/s1; g_rden[n*3+2] = 1.f/s2;
    }
}

// ---------------- per-edge alpha ----------------
__global__ void k_alpha(){
    int i = blockIdx.x*blockDim.x + threadIdx.x;
    if (i >= BE_) return;
    int s = g_esrc[i], d = g_edst[i];
    #pragma unroll
    for (int h = 0; h < 3; h++){
        float e = lrelu(g_asrc[s*3+h] + g_adst[d*3+h]);
        g_alpha[(size_t)i*3+h] = __expf(e - g_max[d*3+h]) * g_rden[d*3+h];
    }
}

// ---------------- aggregation: one block (96 threads) per dst node ----------------
// writes gat (+bias) directly as K-stacked hi/hi/lo bf16 for the proj GEMM
__global__ void k_aggregate(const float* __restrict__ bias_gat){
    int n = blockIdx.x;
    int tid = threadIdx.x;       // 0..95
    int h = tid >> 5;
    int beg = g_off[n], end = g_off[n+1];
    const float4* xp4 = (const float4*)g_xp;
    float4 acc = make_float4(0.f, 0.f, 0.f, 0.f);
    for (int i = beg; i < end; i++){
        int s = g_esrc[i];
        float al = g_alpha[(size_t)i*3 + h];
        float4 v = xp4[(size_t)s*96 + tid];
        acc.x = fmaf(v.x, al, acc.x);
        acc.y = fmaf(v.y, al, acc.y);
        acc.z = fmaf(v.z, al, acc.z);
        acc.w = fmaf(v.w, al, acc.w);
    }
    float es  = lrelu(g_asrc[n*3+h] + g_adst[n*3+h]);
    float als = __expf(es - g_max[n*3+h]) * g_rden[n*3+h];
    float4 v = xp4[(size_t)n*96 + tid];
    acc.x = fmaf(v.x, als, acc.x);
    acc.y = fmaf(v.y, als, acc.y);
    acc.z = fmaf(v.z, als, acc.z);
    acc.w = fmaf(v.w, als, acc.w);
    float4 bg = ((const float4*)bias_gat)[tid];
    acc.x += bg.x; acc.y += bg.y; acc.z += bg.z; acc.w += bg.w;

    int b = n / N_;
    int k = n - b*N_;
    size_t rbase = (size_t)b * K3_PJ * F_;
    float rv[4] = {acc.x, acc.y, acc.z, acc.w};
    union { __nv_bfloat16 bv[4]; uint2 u; } hh, ll;
    #pragma unroll
    for (int j = 0; j < 4; j++){
        __nv_bfloat16 hb = __float2bfloat16(rv[j]);
        hh.bv[j] = hb;
        ll.bv[j] = __float2bfloat16(rv[j] - __bfloat162float(hb));
    }
    *(uint2*)&g_gat3[rbase + (size_t)k*F_            + tid*4] = hh.u;
    *(uint2*)&g_gat3[rbase + (size_t)(20000 + k)*F_  + tid*4] = hh.u;
    *(uint2*)&g_gat3[rbase + (size_t)(40000 + k)*F_  + tid*4] = ll.u;
}

// ---------------- host launch ----------------
extern "C" void kernel_launch(void* const* d_in, const int* in_sizes, int n_in,
                              void* d_out, int out_size){
    const float* x_enc    = (const float*)d_in[0];
    const float* mask     = (const float*)d_in[1];
    const int*   ei       = (const int*)  d_in[2];
    const float* Wq       = (const float*)d_in[3];
    const float* bq       = (const float*)d_in[4];
    const float* Wm       = (const float*)d_in[5];
    const float* bm       = (const float*)d_in[6];
    const float* Wlin     = (const float*)d_in[7];
    const float* att_src  = (const float*)d_in[8];
    const float* att_dst  = (const float*)d_in[9];
    const float* bias_gat = (const float*)d_in[10];
    const float* Wproj    = (const float*)d_in[11];
    const float* bproj    = (const float*)d_in[12];
    const float* Wtemp    = (const float*)d_in[13];
    const float* btemp    = (const float*)d_in[14];
    float* out = (float*)d_out;

    void *pY=nullptr, *pY3=nullptr, *pWq3=nullptr, *pWp3=nullptr, *pG3=nullptr, *pXp=nullptr, *pTmp=nullptr;
    cudaGetSymbolAddress(&pY,   g_Y);
    cudaGetSymbolAddress(&pY3,  g_Y3);
    cudaGetSymbolAddress(&pWq3, g_Wq3);
    cudaGetSymbolAddress(&pWp3, g_Wp3);
    cudaGetSymbolAddress(&pG3,  g_gat3);
    cudaGetSymbolAddress(&pXp,  g_xp);
    cudaGetSymbolAddress(&pTmp, g_tmp);

    // setup + conversions
    k_zero<<<(BN_ + 255)/256, 256>>>();
    k_uvw<<<3, 128>>>(Wlin, Wm, bm);
    k_split_wq<<<(int)(((long)N_*S_ + 255)/256), 256>>>(Wq);
    k_split_wp<<<(int)(((long)S_*N_ + 255)/256), 256>>>(Wproj);

    // Y = x_enc @ Wlin^T  (fp32, small), then hi/lo split
    k_gemm_bt<<<dim3(F_/64, S_/64, B_), 256>>>(
        x_enc, S_*D_, Wlin, (float*)pY, S_*F_, D_, F_, nullptr);
    k_split_Y<<<(B_*S_*F_ + 255)/256, 256>>>();

    // CSR build
    k_count<<<(BE_ + 255)/256, 256>>>(ei);
    k_scan<<<1, 1024>>>();
    k_scatter<<<(BE_ + 255)/256, 256>>>(ei);

    // xp = Wq @ Y + fused affine terms  (bf16 split MMA, K3=1536)
    k_mma<false><<<dim3(F_/128, (N_ + 127)/128, B_), 256>>>(
        (const __nv_bfloat16*)pWq3, K3_XP, N_,
        (const __nv_bfloat16*)pY3, (size_t)K3_XP*F_,
        (float*)pXp, N_*F_,
        1, K3_XP, NITER_XP, bq, mask);

    // attention scalars, softmax stats, per-edge alpha
    k_attn<<<(BN_*H_*32 + 127)/128, 128>>>(att_src, att_dst);
    k_softmax<<<(BN_*32 + 127)/128, 128>>>();
    k_alpha<<<(BE_ + 255)/256, 256>>>();

    // GAT aggregation -> gat3 (bf16 hi/hi/lo)
    k_aggregate<<<BN_, 96>>>(bias_gat);

    // projection: tmp = bproj + Wproj @ gat  (bf16 split MMA, K3=60000, split-K=25)
    k_tmpinit<<<(B_*S_*F_ + 255)/256, 256>>>(bproj);
    k_mma<true><<<dim3(F_/128, S_/128, B_*NSPLIT), 256>>>(
        (const __nv_bfloat16*)pWp3, K3_PJ, S_,
        (const __nv_bfloat16*)pG3, (size_t)K3_PJ*F_,
        (float*)pTmp, S_*F_,
        NSPLIT, KCHUNK, NITER_PJ, nullptr, nullptr);

    // final: out = tmp @ Wtemp^T + btemp
    k_gemm_bt<<<dim3(DG_/64, (B_*S_)/64, 1), 256>>>(
        (const float*)pTmp, 0, Wtemp, out, 0, F_, DG_, btemp);
}

// round 3
// speedup vs baseline: 1.7917x; 1.0053x over previous
#include <cuda_runtime.h>
#include <cuda_bf16.h>
#include <math.h>

#define B_  2
#define S_  512
#define N_  20000
#define D_  384
#define H_  3
#define C_  128
#define F_  384        // H*C
#define E_  320000
#define DG_ 128
#define BN_ (B_*N_)    // 40000
#define BE_ (B_*E_)    // 640000

#define K3_XP   1536          // 3*512
#define K3_PJ   60000         // 3*20000
#define NSPLIT  25
#define KCHUNK  2400          // 60000/25, 75 iters of 32
#define NITER_PJ 75
#define NITER_XP 48

// ---------------- device scratch (static, no allocation) ----------------
__device__ float g_Y[B_*S_*F_];                       // x_enc @ Wlin^T  [2,512,384] fp32
__device__ __align__(16) __nv_bfloat16 g_Y3[B_*K3_XP*F_];     // hi;hi;lo  [2,1536,384]
__device__ __align__(16) __nv_bfloat16 g_Wq3[(size_t)N_*K3_XP];      // hi|lo|hi  [20000,1536]
__device__ __align__(16) __nv_bfloat16 g_Wp3[(size_t)S_*K3_PJ];      // hi|lo|hi  [512,60000]
__device__ __align__(16) __nv_bfloat16 g_gat3[(size_t)B_*K3_PJ*F_];  // hi;hi;lo  [2,60000,384]
__device__ float g_uvw[3*F_];
__device__ float g_xp[(size_t)BN_*F_];
__device__ float g_asrc[BN_*H_];
__device__ float g_adst[BN_*H_];
__device__ float g_max[BN_*H_];
__device__ float g_rden[BN_*H_];
__device__ int   g_off[BN_+1];
__device__ int   g_cnt[BN_];
__device__ int   g_cur[BN_];
__device__ int   g_esrc[BE_];
__device__ int   g_edst[BE_];
__device__ float g_alpha[(size_t)BE_*H_];
__device__ float g_tmp[B_*S_*F_];

__device__ __forceinline__ float lrelu(float x){ return x > 0.f ? x : 0.2f*x; }

// ---------------- PTX helpers ----------------
__device__ __forceinline__ unsigned su(const void* p){
    return (unsigned)__cvta_generic_to_shared(p);
}
__device__ __forceinline__ void cpa16(unsigned dst, const void* src, bool pred){
    int sz = pred ? 16 : 0;
    asm volatile("cp.async.cg.shared.global [%0], [%1], 16, %2;\n"
                 :: "r"(dst), "l"(src), "r"(sz));
}
__device__ __forceinline__ void cp_commit(){ asm volatile("cp.async.commit_group;\n"); }
__device__ __forceinline__ void cp_wait1(){ asm volatile("cp.async.wait_group 1;\n"); }
__device__ __forceinline__ void ldsm4(unsigned addr, unsigned &r0, unsigned &r1, unsigned &r2, unsigned &r3){
    asm volatile("ldmatrix.sync.aligned.m8n8.x4.shared.b16 {%0,%1,%2,%3}, [%4];\n"
                 : "=r"(r0),"=r"(r1),"=r"(r2),"=r"(r3) : "r"(addr));
}
__device__ __forceinline__ void ldsm4t(unsigned addr, unsigned &r0, unsigned &r1, unsigned &r2, unsigned &r3){
    asm volatile("ldmatrix.sync.aligned.m8n8.x4.trans.shared.b16 {%0,%1,%2,%3}, [%4];\n"
                 : "=r"(r0),"=r"(r1),"=r"(r2),"=r"(r3) : "r"(addr));
}
__device__ __forceinline__ void mma16816(float* c, const unsigned* a, const unsigned* b){
    asm volatile("mma.sync.aligned.m16n8k16.row.col.f32.bf16.bf16.f32 "
                 "{%0,%1,%2,%3},{%4,%5,%6,%7},{%8,%9},{%0,%1,%2,%3};\n"
                 : "+f"(c[0]),"+f"(c[1]),"+f"(c[2]),"+f"(c[3])
                 : "r"(a[0]),"r"(a[1]),"r"(a[2]),"r"(a[3]),"r"(b[0]),"r"(b[1]));
}

// ---------------- tiny setup kernels ----------------
__global__ void k_zero(){
    int i = blockIdx.x*blockDim.x + threadIdx.x;
    if (i < BN_){ g_cnt[i] = 0; g_cur[i] = 0; }
}

__global__ void k_uvw(const float* __restrict__ Wlin,
                      const float* __restrict__ Wm,
                      const float* __restrict__ bm){
    int f = blockIdx.x*blockDim.x + threadIdx.x;
    if (f >= F_) return;
    float u = 0.f, v = 0.f, w = 0.f;
    for (int d = 0; d < D_; d++){
        float wl = Wlin[f*D_ + d];
        u += wl * Wm[d];
        v += wl * bm[d];
        w += wl;
    }
    g_uvw[f] = u; g_uvw[F_+f] = v; g_uvw[2*F_+f] = w;
}

__global__ void k_tmpinit(const float* __restrict__ bproj){
    int i = blockIdx.x*blockDim.x + threadIdx.x;
    if (i >= B_*S_*F_) return;
    int s = (i / F_) % S_;
    g_tmp[i] = bproj[s];
}

// ---------------- hi/lo split conversions ----------------
__global__ void k_split_wq(const float* __restrict__ Wq){
    long i = (long)blockIdx.x*blockDim.x + threadIdx.x;
    if (i >= (long)N_*S_) return;
    int m = (int)(i / S_), k = (int)(i - (long)m*S_);
    float x = Wq[i];
    __nv_bfloat16 h = __float2bfloat16(x);
    __nv_bfloat16 l = __float2bfloat16(x - __bfloat162float(h));
    size_t base = (size_t)m*K3_XP;
    g_Wq3[base + k]        = h;
    g_Wq3[base + 512 + k]  = l;
    g_Wq3[base + 1024 + k] = h;
}

__global__ void k_split_wp(const float* __restrict__ Wproj){
    long i = (long)blockIdx.x*blockDim.x + threadIdx.x;
    if (i >= (long)S_*N_) return;
    int m = (int)(i / N_), k = (int)(i - (long)m*N_);
    float x = Wproj[i];
    __nv_bfloat16 h = __float2bfloat16(x);
    __nv_bfloat16 l = __float2bfloat16(x - __bfloat162float(h));
    size_t base = (size_t)m*K3_PJ;
    g_Wp3[base + k]          = h;
    g_Wp3[base + 20000 + k]  = l;
    g_Wp3[base + 40000 + k]  = h;
}

__global__ void k_split_Y(){
    int i = blockIdx.x*blockDim.x + threadIdx.x;
    if (i >= B_*S_*F_) return;
    int b = i / (S_*F_);
    int r = (i / F_) % S_;
    int n = i % F_;
    float x = g_Y[i];
    __nv_bfloat16 h = __float2bfloat16(x);
    __nv_bfloat16 l = __float2bfloat16(x - __bfloat162float(h));
    size_t base = (size_t)b*K3_XP*F_;
    g_Y3[base + (size_t)r*F_ + n]          = h;
    g_Y3[base + (size_t)(512 + r)*F_ + n]  = h;
    g_Y3[base + (size_t)(1024 + r)*F_ + n] = l;
}

// ---------------- fp32 tiled GEMM (small matrices only), C = A @ Bm^T (+bias_col) ----------------
__global__ void k_gemm_bt(const float* __restrict__ A, int strideA,
                          const float* __restrict__ Bm,
                          float* __restrict__ C, int strideC,
                          int K, int Ncol,
                          const float* __restrict__ bias_col){
    const float* Ab = A + blockIdx.z * strideA;
    float* Cb = C + blockIdx.z * strideC;
    int m0 = blockIdx.y*64, n0 = blockIdx.x*64;
    __shared__ float As[16][64];
    __shared__ float Bs[16][64];
    int tid  = threadIdx.x;
    int tm   = tid >> 4, tn = tid & 15;
    int lrow = tid >> 2;
    int lcol = (tid & 3) * 4;
    float acc[4][4] = {};
    for (int k0 = 0; k0 < K; k0 += 16){
        float4 av = *(const float4*)(Ab + (m0 + lrow)*K + k0 + lcol);
        As[lcol+0][lrow]=av.x; As[lcol+1][lrow]=av.y; As[lcol+2][lrow]=av.z; As[lcol+3][lrow]=av.w;
        float4 bv = *(const float4*)(Bm + (n0 + lrow)*K + k0 + lcol);
        Bs[lcol+0][lrow]=bv.x; Bs[lcol+1][lrow]=bv.y; Bs[lcol+2][lrow]=bv.z; Bs[lcol+3][lrow]=bv.w;
        __syncthreads();
        #pragma unroll
        for (int kk = 0; kk < 16; kk++){
            float4 a4 = *(const float4*)&As[kk][tm*4];
            float4 b4 = *(const float4*)&Bs[kk][tn*4];
            float ar[4] = {a4.x,a4.y,a4.z,a4.w};
            float br[4] = {b4.x,b4.y,b4.z,b4.w};
            #pragma unroll
            for (int i = 0; i < 4; i++)
                #pragma unroll
                for (int j = 0; j < 4; j++)
                    acc[i][j] = fmaf(ar[i], br[j], acc[i][j]);
        }
        __syncthreads();
    }
    #pragma unroll
    for (int i = 0; i < 4; i++){
        int row = m0 + tm*4 + i;
        #pragma unroll
        for (int j = 0; j < 4; j++){
            int col = n0 + tn*4 + j;
            float v = acc[i][j];
            if (bias_col) v += bias_col[col];
            Cb[row*Ncol + col] = v;
        }
    }
}

// ---------------- bf16 tensor-core GEMM, 128x128x32 tiles, 2-stage cp.async ----------------
// C[M,384] (+= / =) A[M,lda] @ B[K3,384],  bf16 operands, fp32 accumulate.
// ATOMIC=false: xp epilogue (fused bq*w + mask*u + v, direct store)
// ATOMIC=true : split-K atomicAdd epilogue
template<bool ATOMIC>
__global__ __launch_bounds__(256, 2)
void k_mma(const __nv_bfloat16* __restrict__ A, int lda, int M,
           const __nv_bfloat16* __restrict__ Bbase, size_t strideB,
           float* __restrict__ Cbase, int strideC,
           int nsplit, int kchunk, int niter,
           const float* __restrict__ bq, const float* __restrict__ mask)
{
    __shared__ __align__(16) __nv_bfloat16 sA[2][128][40];
    __shared__ __align__(16) __nv_bfloat16 sB[2][32][136];

    int bz = blockIdx.z / nsplit, sp = blockIdx.z % nsplit;
    int kbeg = sp * kchunk;
    int m0 = blockIdx.y * 128, n0 = blockIdx.x * 128;
    const __nv_bfloat16* Bp = Bbase + (size_t)bz * strideB;
    float* C = Cbase + (size_t)bz * strideC;

    int tid = threadIdx.x, lane = tid & 31, wid = tid >> 5;
    int wm = wid & 3, wn = wid >> 2;      // 4 x 2 warp grid, warp tile 32m x 64n

    auto load_stage = [&](int st, int kpos){
        #pragma unroll
        for (int c = tid; c < 512; c += 256){       // A tile: 128 x 32
            int row = c >> 2, seg = c & 3;
            int gr = m0 + row;
            const void* src = A + (size_t)(gr < M ? gr : M-1) * lda + kpos + seg*8;
            cpa16(su(&sA[st][row][seg*8]), src, gr < M);
        }
        #pragma unroll
        for (int c = tid; c < 512; c += 256){       // B tile: 32 x 128
            int row = c >> 4, seg = c & 15;
            const void* src = Bp + (size_t)(kpos + row) * F_ + n0 + seg*8;
            cpa16(su(&sB[st][row][seg*8]), src, true);
        }
    };

    float acc[2][8][4] = {};

    load_stage(0, kbeg);
    cp_commit();

    for (int it = 0; it < niter; ++it){
        if (it + 1 < niter) load_stage((it+1)&1, kbeg + (it+1)*32);
        cp_commit();
        cp_wait1();
        __syncthreads();
        int st = it & 1;
        int lrow = lane & 15, lhi = lane >> 4;
        #pragma unroll
        for (int kk = 0; kk < 2; ++kk){
            int k0 = kk*16;
            unsigned a[2][4], b[8][2];
            #pragma unroll
            for (int mi = 0; mi < 2; ++mi){
                unsigned addr = su(&sA[st][wm*32 + mi*16 + lrow][k0 + lhi*8]);
                ldsm4(addr, a[mi][0], a[mi][1], a[mi][2], a[mi][3]);
            }
            #pragma unroll
            for (int nt = 0; nt < 4; ++nt){
                unsigned addr = su(&sB[st][k0 + lrow][wn*64 + nt*16 + lhi*8]);
                unsigned r0,r1,r2,r3;
                ldsm4t(addr, r0,r1,r2,r3);
                b[nt*2  ][0]=r0; b[nt*2  ][1]=r1;
                b[nt*2+1][0]=r2; b[nt*2+1][1]=r3;
            }
            #pragma unroll
            for (int mi = 0; mi < 2; ++mi)
                #pragma unroll
                for (int ni = 0; ni < 8; ++ni)
                    mma16816(acc[mi][ni], a[mi], b[ni]);
        }
        __syncthreads();
    }

    // epilogue
    int g = lane >> 2, tig = lane & 3;
    #pragma unroll
    for (int mi = 0; mi < 2; ++mi){
        #pragma unroll
        for (int half = 0; half < 2; ++half){
            int row = m0 + wm*32 + mi*16 + g + half*8;
            if (row >= M) continue;
            float bqv = 0.f, mv = 0.f;
            if constexpr (!ATOMIC){
                bqv = bq[row];
                mv  = mask[bz*N_ + row];
            }
            #pragma unroll
            for (int ni = 0; ni < 8; ++ni){
                int col = n0 + wn*64 + ni*8 + tig*2;
                float v0 = acc[mi][ni][half*2+0];
                float v1 = acc[mi][ni][half*2+1];
                if constexpr (ATOMIC){
                    atomicAdd(&C[(size_t)row*F_ + col],     v0);
                    atomicAdd(&C[(size_t)row*F_ + col + 1], v1);
                } else {
                    v0 += bqv*g_uvw[2*F_+col]   + mv*g_uvw[col]   + g_uvw[F_+col];
                    v1 += bqv*g_uvw[2*F_+col+1] + mv*g_uvw[col+1] + g_uvw[F_+col+1];
                    *(float2*)&C[(size_t)row*F_ + col] = make_float2(v0, v1);
                }
            }
        }
    }
}

// ---------------- attention scalars ----------------
__global__ void k_attn(const float* __restrict__ att_src,
                       const float* __restrict__ att_dst){
    int gw = (blockIdx.x*blockDim.x + threadIdx.x) >> 5;
    if (gw >= BN_*H_) return;
    int lane = threadIdx.x & 31;
    int n = gw / H_, h = gw % H_;
    const float* xrow = g_xp + (size_t)n*F_ + h*C_;
    float s1 = 0.f, s2 = 0.f;
    #pragma unroll
    for (int k = 0; k < 4; k++){
        int c = lane + k*32;
        float xv = xrow[c];
        s1 = fmaf(xv, att_src[h*C_ + c], s1);
        s2 = fmaf(xv, att_dst[h*C_ + c], s2);
    }
    #pragma unroll
    for (int o = 16; o; o >>= 1){
        s1 += __shfl_xor_sync(0xffffffffu, s1, o);
        s2 += __shfl_xor_sync(0xffffffffu, s2, o);
    }
    if (lane == 0){ g_asrc[n*H_+h] = s1; g_adst[n*H_+h] = s2; }
}

// ---------------- CSR build ----------------
__global__ void k_count(const int* __restrict__ ei){
    int e = blockIdx.x*blockDim.x + threadIdx.x;
    if (e >= BE_) return;
    int b = e / E_, j = e - b*E_;
    int dst = ei[E_ + j] + b*N_;
    atomicAdd(&g_cnt[dst], 1);
}

__global__ void k_scan(){
    __shared__ int ssum[1024];
    int tid = threadIdx.x;
    const int CH = (BN_ + 1023) / 1024;
    int base = tid * CH;
    int s = 0;
    for (int i = 0; i < CH; i++){
        int idx = base + i;
        if (idx < BN_) s += g_cnt[idx];
    }
    ssum[tid] = s;
    __syncthreads();
    for (int off = 1; off < 1024; off <<= 1){
        int v = (tid >= off) ? ssum[tid - off] : 0;
        __syncthreads();
        ssum[tid] += v;
        __syncthreads();
    }
    int run = ssum[tid] - s;
    for (int i = 0; i < CH; i++){
        int idx = base + i;
        if (idx < BN_){ g_off[idx] = run; run += g_cnt[idx]; }
    }
    if (tid == 1023) g_off[BN_] = ssum[1023];
}

__global__ void k_scatter(const int* __restrict__ ei){
    int e = blockIdx.x*blockDim.x + threadIdx.x;
    if (e >= BE_) return;
    int b = e / E_, j = e - b*E_;
    int src = ei[j]       + b*N_;
    int dst = ei[E_ + j]  + b*N_;
    int pos = g_off[dst] + atomicAdd(&g_cur[dst], 1);
    g_esrc[pos] = src;
    g_edst[pos] = dst;
}

// ---------------- per-node segment softmax stats ----------------
__global__ void k_softmax(){
    int gw = (blockIdx.x*blockDim.x + threadIdx.x) >> 5;
    if (gw >= BN_) return;
    int lane = threadIdx.x & 31;
    int n = gw;
    float ad0 = g_adst[n*3+0], ad1 = g_adst[n*3+1], ad2 = g_adst[n*3+2];
    float e0s = lrelu(g_asrc[n*3+0] + ad0);
    float e1s = lrelu(g_asrc[n*3+1] + ad1);
    float e2s = lrelu(g_asrc[n*3+2] + ad2);
    float m0 = e0s, m1 = e1s, m2 = e2s;
    int beg = g_off[n], end = g_off[n+1];
    for (int i = beg + lane; i < end; i += 32){
        int s = g_esrc[i];
        m0 = fmaxf(m0, lrelu(g_asrc[s*3+0] + ad0));
        m1 = fmaxf(m1, lrelu(g_asrc[s*3+1] + ad1));
        m2 = fmaxf(m2, lrelu(g_asrc[s*3+2] + ad2));
    }
    #pragma unroll
    for (int o = 16; o; o >>= 1){
        m0 = fmaxf(m0, __shfl_xor_sync(0xffffffffu, m0, o));
        m1 = fmaxf(m1, __shfl_xor_sync(0xffffffffu, m1, o));
        m2 = fmaxf(m2, __shfl_xor_sync(0xffffffffu, m2, o));
    }
    float s0 = 0.f, s1 = 0.f, s2 = 0.f;
    for (int i = beg + lane; i < end; i += 32){
        int s = g_esrc[i];
        s0 += __expf(lrelu(g_asrc[s*3+0] + ad0) - m0);
        s1 += __expf(lrelu(g_asrc[s*3+1] + ad1) - m1);
        s2 += __expf(lrelu(g_asrc[s*3+2] + ad2) - m2);
    }
    #pragma unroll
    for (int o = 16; o; o >>= 1){
        s0 += __shfl_xor_sync(0xffffffffu, s0, o);
        s1 += __shfl_xor_sync(0xffffffffu, s1, o);
        s2 += __shfl_xor_sync(0xffffffffu, s2, o);
    }
    if (lane == 0){
        s0 += __expf(e0s - m0);
        s1 += __expf(e1s - m1);
        s2 += __expf(e2s - m2);
        g_max[n*3+0] = m0; g_max[n*3+1] = m1; g_max[n*3+2] = m2;
        g_rden[n*3+0] = 1.f/s0; g_rden[n*3+1] = 1.f/s1; g_rden[n*3+2] = 1.f/s2;
    }
}

// ---------------- per-edge alpha ----------------
__global__ void k_alpha(){
    int i = blockIdx.x*blockDim.x + threadIdx.x;
    if (i >= BE_) return;
    int s = g_esrc[i], d = g_edst[i];
    #pragma unroll
    for (int h = 0; h < 3; h++){
        float e = lrelu(g_asrc[s*3+h] + g_adst[d*3+h]);
        g_alpha[(size_t)i*3+h] = __expf(e - g_max[d*3+h]) * g_rden[d*3+h];
    }
}

// ---------------- aggregation: one block (96 threads) per dst node ----------------
// writes gat (+bias) directly as K-stacked hi/hi/lo bf16 for the proj GEMM
__global__ void k_aggregate(const float* __restrict__ bias_gat){
    int n = blockIdx.x;
    int tid = threadIdx.x;       // 0..95
    int h = tid >> 5;
    int beg = g_off[n], end = g_off[n+1];
    const float4* xp4 = (const float4*)g_xp;
    float4 acc = make_float4(0.f, 0.f, 0.f, 0.f);
    for (int i = beg; i < end; i++){
        int s = g_esrc[i];
        float al = g_alpha[(size_t)i*3 + h];
        float4 v = xp4[(size_t)s*96 + tid];
        acc.x = fmaf(v.x, al, acc.x);
        acc.y = fmaf(v.y, al, acc.y);
        acc.z = fmaf(v.z, al, acc.z);
        acc.w = fmaf(v.w, al, acc.w);
    }
    float es  = lrelu(g_asrc[n*3+h] + g_adst[n*3+h]);
    float als = __expf(es - g_max[n*3+h]) * g_rden[n*3+h];
    float4 v = xp4[(size_t)n*96 + tid];
    acc.x = fmaf(v.x, als, acc.x);
    acc.y = fmaf(v.y, als, acc.y);
    acc.z = fmaf(v.z, als, acc.z);
    acc.w = fmaf(v.w, als, acc.w);
    float4 bg = ((const float4*)bias_gat)[tid];
    acc.x += bg.x; acc.y += bg.y; acc.z += bg.z; acc.w += bg.w;

    int b = n / N_;
    int k = n - b*N_;
    size_t rbase = (size_t)b * K3_PJ * F_;
    float rv[4] = {acc.x, acc.y, acc.z, acc.w};
    union { __nv_bfloat16 bv[4]; uint2 u; } hh, ll;
    #pragma unroll
    for (int j = 0; j < 4; j++){
        __nv_bfloat16 hb = __float2bfloat16(rv[j]);
        hh.bv[j] = hb;
        ll.bv[j] = __float2bfloat16(rv[j] - __bfloat162float(hb));
    }
    *(uint2*)&g_gat3[rbase + (size_t)k*F_            + tid*4] = hh.u;
    *(uint2*)&g_gat3[rbase + (size_t)(20000 + k)*F_  + tid*4] = hh.u;
    *(uint2*)&g_gat3[rbase + (size_t)(40000 + k)*F_  + tid*4] = ll.u;
}

// ---------------- host launch ----------------
extern "C" void kernel_launch(void* const* d_in, const int* in_sizes, int n_in,
                              void* d_out, int out_size){
    const float* x_enc    = (const float*)d_in[0];
    const float* mask     = (const float*)d_in[1];
    const int*   ei       = (const int*)  d_in[2];
    const float* Wq       = (const float*)d_in[3];
    const float* bq       = (const float*)d_in[4];
    const float* Wm       = (const float*)d_in[5];
    const float* bm       = (const float*)d_in[6];
    const float* Wlin     = (const float*)d_in[7];
    const float* att_src  = (const float*)d_in[8];
    const float* att_dst  = (const float*)d_in[9];
    const float* bias_gat = (const float*)d_in[10];
    const float* Wproj    = (const float*)d_in[11];
    const float* bproj    = (const float*)d_in[12];
    const float* Wtemp    = (const float*)d_in[13];
    const float* btemp    = (const float*)d_in[14];
    float* out = (float*)d_out;

    void *pY=nullptr, *pY3=nullptr, *pWq3=nullptr, *pWp3=nullptr, *pG3=nullptr, *pXp=nullptr, *pTmp=nullptr;
    cudaGetSymbolAddress(&pY,   g_Y);
    cudaGetSymbolAddress(&pY3,  g_Y3);
    cudaGetSymbolAddress(&pWq3, g_Wq3);
    cudaGetSymbolAddress(&pWp3, g_Wp3);
    cudaGetSymbolAddress(&pG3,  g_gat3);
    cudaGetSymbolAddress(&pXp,  g_xp);
    cudaGetSymbolAddress(&pTmp, g_tmp);

    // setup + conversions
    k_zero<<<(BN_ + 255)/256, 256>>>();
    k_uvw<<<3, 128>>>(Wlin, Wm, bm);
    k_split_wq<<<(int)(((long)N_*S_ + 255)/256), 256>>>(Wq);
    k_split_wp<<<(int)(((long)S_*N_ + 255)/256), 256>>>(Wproj);

    // Y = x_enc @ Wlin^T  (fp32, small), then hi/lo split
    k_gemm_bt<<<dim3(F_/64, S_/64, B_), 256>>>(
        x_enc, S_*D_, Wlin, (float*)pY, S_*F_, D_, F_, nullptr);
    k_split_Y<<<(B_*S_*F_ + 255)/256, 256>>>();

    // CSR build
    k_count<<<(BE_ + 255)/256, 256>>>(ei);
    k_scan<<<1, 1024>>>();
    k_scatter<<<(BE_ + 255)/256, 256>>>(ei);

    // xp = Wq @ Y + fused affine terms  (bf16 split MMA, K3=1536)
    k_mma<false><<<dim3(F_/128, (N_ + 127)/128, B_), 256>>>(
        (const __nv_bfloat16*)pWq3, K3_XP, N_,
        (const __nv_bfloat16*)pY3, (size_t)K3_XP*F_,
        (float*)pXp, N_*F_,
        1, K3_XP, NITER_XP, bq, mask);

    // attention scalars, softmax stats, per-edge alpha
    k_attn<<<(BN_*H_*32 + 127)/128, 128>>>(att_src, att_dst);
    k_softmax<<<(BN_*32 + 127)/128, 128>>>();
    k_alpha<<<(BE_ + 255)/256, 256>>>();

    // GAT aggregation -> gat3 (bf16 hi/hi/lo)
    k_aggregate<<<BN_, 96>>>(bias_gat);

    // projection: tmp = bproj + Wproj @ gat  (bf16 split MMA, K3=60000, split-K=25)
    k_tmpinit<<<(B_*S_*F_ + 255)/256, 256>>>(bproj);
    k_mma<true><<<dim3(F_/128, S_/128, B_*NSPLIT), 256>>>(
        (const __nv_bfloat16*)pWp3, K3_PJ, S_,
        (const __nv_bfloat16*)pG3, (size_t)K3_PJ*F_,
        (float*)pTmp, S_*F_,
        NSPLIT, KCHUNK, NITER_PJ, nullptr, nullptr);

    // final: out = tmp @ Wtemp^T + btemp
    k_gemm_bt<<<dim3(DG_/64, (B_*S_)/64, 1), 256>>>(
        (const float*)pTmp, 0, Wtemp, out, 0, F_, DG_, btemp);
}

// round 5
// speedup vs baseline: 2.1085x; 1.1768x over previous
#include <cuda_runtime.h>
#include <cuda_bf16.h>
#include <math.h>
#include <stdint.h>

#define B_  2
#define S_  512
#define N_  20000
#define D_  384
#define H_  3
#define C_  128
#define F_  384
#define E_  320000
#define DG_ 128
#define BN_ (B_*N_)
#define BE_ (B_*E_)

#define NW_      768                  // concat N over batches
#define KV_XP    1536                 // virtual K for xp (3*512)
#define NCH_XP   48
#define KV_PJ    60000                // virtual K for proj (3*20000)
#define NSPLIT_PJ 25
#define KCHUNK_PJ 2400                // 75 iters of 32
#define NCH_PJ   75
#define STG_A    10240                // 128*40*2
#define STG_B    8704                 // 32*136*2
#define STG_SZ   (STG_A+STG_B)        // 18944
#define SMEM_MMA (4*STG_SZ)           // 75776

// ---------------- device scratch ----------------
__device__ __align__(16) __nv_bfloat16 g_Y2[1024*NW_];              // [hi;lo] x [512, 768]
__device__ __align__(16) __nv_bfloat16 g_Wq2[(size_t)N_*1024];      // [20000, hi|lo 1024]
__device__ __align__(16) __nv_bfloat16 g_Wp2[(size_t)S_*40000];     // [512, hi|lo 40000]
__device__ __align__(16) __nv_bfloat16 g_gat2[(size_t)40000*NW_];   // [hi;lo] x [20000, 768]
__device__ float g_uvw[3*F_];
__device__ float g_xp[(size_t)BN_*F_];
__device__ float g_asrc[BN_*H_];
__device__ float g_adst[BN_*H_];
__device__ float g_max[BN_*H_];
__device__ float g_rden[BN_*H_];
__device__ int   g_off[BN_+1];
__device__ int   g_cnt[BN_];
__device__ int   g_cur[BN_];
__device__ int   g_esrc[BE_];
__device__ int   g_edst[BE_];
__device__ float g_alpha[(size_t)BE_*H_];
__device__ float g_tmp[B_*S_*F_];

__device__ __forceinline__ float lrelu(float x){ return x > 0.f ? x : 0.2f*x; }
__device__ __forceinline__ unsigned su(const void* p){
    return (unsigned)__cvta_generic_to_shared(p);
}
__device__ __forceinline__ void cpa16(unsigned dst, const void* src, bool pred){
    int sz = pred ? 16 : 0;
    asm volatile("cp.async.cg.shared.global [%0], [%1], 16, %2;\n"
                 :: "r"(dst), "l"(src), "r"(sz));
}
__device__ __forceinline__ void ldsm4(unsigned addr, unsigned &r0, unsigned &r1, unsigned &r2, unsigned &r3){
    asm volatile("ldmatrix.sync.aligned.m8n8.x4.shared.b16 {%0,%1,%2,%3}, [%4];\n"
                 : "=r"(r0),"=r"(r1),"=r"(r2),"=r"(r3) : "r"(addr));
}
__device__ __forceinline__ void ldsm4t(unsigned addr, unsigned &r0, unsigned &r1, unsigned &r2, unsigned &r3){
    asm volatile("ldmatrix.sync.aligned.m8n8.x4.trans.shared.b16 {%0,%1,%2,%3}, [%4];\n"
                 : "=r"(r0),"=r"(r1),"=r"(r2),"=r"(r3) : "r"(addr));
}
__device__ __forceinline__ void mma16816(float* c, const unsigned* a, const unsigned* b){
    asm volatile("mma.sync.aligned.m16n8k16.row.col.f32.bf16.bf16.f32 "
                 "{%0,%1,%2,%3},{%4,%5,%6,%7},{%8,%9},{%0,%1,%2,%3};\n"
                 : "+f"(c[0]),"+f"(c[1]),"+f"(c[2]),"+f"(c[3])
                 : "r"(a[0]),"r"(a[1]),"r"(a[2]),"r"(a[3]),"r"(b[0]),"r"(b[1]));
}

// ---------------- small kernels ----------------
__global__ void k_zero(){
    int i = blockIdx.x*blockDim.x + threadIdx.x;
    if (i < BN_){ g_cnt[i] = 0; g_cur[i] = 0; }
}
__global__ void k_uvw(const float* __restrict__ Wlin, const float* __restrict__ Wm,
                      const float* __restrict__ bm){
    int f = blockIdx.x*blockDim.x + threadIdx.x;
    if (f >= F_) return;
    float u=0.f, v=0.f, w=0.f;
    for (int d = 0; d < D_; d++){
        float wl = Wlin[f*D_ + d];
        u += wl*Wm[d]; v += wl*bm[d]; w += wl;
    }
    g_uvw[f]=u; g_uvw[F_+f]=v; g_uvw[2*F_+f]=w;
}
__global__ void k_tmpinit(const float* __restrict__ bproj){
    int i = blockIdx.x*blockDim.x + threadIdx.x;
    if (i >= B_*S_*F_) return;
    g_tmp[i] = bproj[(i / F_) % S_];
}

// ---------------- vectorized hi/lo weight splits ----------------
__global__ void k_split_wq2(const float* __restrict__ Wq){
    int i4 = blockIdx.x*blockDim.x + threadIdx.x;      // 2.56M
    if (i4 >= N_*(S_/4)) return;
    int m = i4 >> 7, k = (i4 & 127) << 2;
    float4 x = *(const float4*)(Wq + (size_t)m*S_ + k);
    float xs[4] = {x.x, x.y, x.z, x.w};
    union { __nv_bfloat16 b[4]; uint2 u; } hh, ll;
    #pragma unroll
    for (int j = 0; j < 4; j++){
        __nv_bfloat16 h = __float2bfloat16(xs[j]);
        hh.b[j] = h;
        ll.b[j] = __float2bfloat16(xs[j] - __bfloat162float(h));
    }
    size_t base = (size_t)m*1024;
    *(uint2*)&g_Wq2[base + k]       = hh.u;
    *(uint2*)&g_Wq2[base + 512 + k] = ll.u;
}
__global__ void k_split_wp2(const float* __restrict__ Wproj){
    int i4 = blockIdx.x*blockDim.x + threadIdx.x;      // 2.56M
    if (i4 >= S_*(N_/4)) return;
    int m = i4 / 5000, k = (i4 % 5000) << 2;
    float4 x = *(const float4*)(Wproj + (size_t)m*N_ + k);
    float xs[4] = {x.x, x.y, x.z, x.w};
    union { __nv_bfloat16 b[4]; uint2 u; } hh, ll;
    #pragma unroll
    for (int j = 0; j < 4; j++){
        __nv_bfloat16 h = __float2bfloat16(xs[j]);
        hh.b[j] = h;
        ll.b[j] = __float2bfloat16(xs[j] - __bfloat162float(h));
    }
    size_t base = (size_t)m*40000;
    *(uint2*)&g_Wp2[base + k]         = hh.u;
    *(uint2*)&g_Wp2[base + 20000 + k] = ll.u;
}

// ---------------- fp32 tiled GEMM (small), C = A @ Bm^T ----------------
// If Ysplit != null: write hi/lo K-stacked bf16 into Y2 [1024, 768] at col z*384+f.
__global__ void k_gemm_bt(const float* __restrict__ A, int strideA,
                          const float* __restrict__ Bm,
                          float* __restrict__ C, int strideC,
                          int K, int Ncol, const float* __restrict__ bias_col,
                          __nv_bfloat16* __restrict__ Ysplit){
    const float* Ab = A + blockIdx.z * strideA;
    int m0 = blockIdx.y*64, n0 = blockIdx.x*64;
    __shared__ float As[16][64];
    __shared__ float Bs[16][64];
    int tid = threadIdx.x;
    int tm = tid >> 4, tn = tid & 15;
    int lrow = tid >> 2, lcol = (tid & 3)*4;
    float acc[4][4] = {};
    for (int k0 = 0; k0 < K; k0 += 16){
        float4 av = *(const float4*)(Ab + (m0+lrow)*K + k0 + lcol);
        As[lcol+0][lrow]=av.x; As[lcol+1][lrow]=av.y; As[lcol+2][lrow]=av.z; As[lcol+3][lrow]=av.w;
        float4 bv = *(const float4*)(Bm + (n0+lrow)*K + k0 + lcol);
        Bs[lcol+0][lrow]=bv.x; Bs[lcol+1][lrow]=bv.y; Bs[lcol+2][lrow]=bv.z; Bs[lcol+3][lrow]=bv.w;
        __syncthreads();
        #pragma unroll
        for (int kk = 0; kk < 16; kk++){
            float4 a4 = *(const float4*)&As[kk][tm*4];
            float4 b4 = *(const float4*)&Bs[kk][tn*4];
            float ar[4]={a4.x,a4.y,a4.z,a4.w}, br[4]={b4.x,b4.y,b4.z,b4.w};
            #pragma unroll
            for (int i=0;i<4;i++)
                #pragma unroll
                for (int j=0;j<4;j++) acc[i][j]=fmaf(ar[i],br[j],acc[i][j]);
        }
        __syncthreads();
    }
    #pragma unroll
    for (int i=0;i<4;i++){
        int row = m0 + tm*4 + i;
        #pragma unroll
        for (int j=0;j<4;j++){
            int col = n0 + tn*4 + j;
            float v = acc[i][j];
            if (Ysplit){
                __nv_bfloat16 h = __float2bfloat16(v);
                int gc = blockIdx.z*384 + col;
                Ysplit[(size_t)row*NW_ + gc]         = h;
                Ysplit[(size_t)(512 + row)*NW_ + gc] = __float2bfloat16(v - __bfloat162float(h));
            } else {
                v += bias_col[col];
                (C + blockIdx.z*strideC)[row*Ncol + col] = v;
            }
        }
    }
}

// ---------------- bf16 mma.sync GEMM: CTA 128x128, 4 warps 64x64, 4-stage cp.async ----
// A [M,lda] row-major bf16 ([hi|lo], virtual-K remap TA)
// B [Kb, NW_] row-major bf16 ([hi;lo] stacked K, remap TB)
// EPI=0: xp (fused affine -> g_xp); EPI=1: proj (atomicAdd -> g_tmp)
template<int EPI>
__global__ __launch_bounds__(128, 2)
void k_mma(const __nv_bfloat16* __restrict__ A, int lda, int M, int TA,
           const __nv_bfloat16* __restrict__ Bm, int TB,
           int kchunk, int nchunks,
           const float* __restrict__ bq, const float* __restrict__ mask)
{
    extern __shared__ __align__(16) char smem[];
    uint32_t sbase = su(smem);

    const int tid = threadIdx.x, lane = tid & 31, wid = tid >> 5;
    const int wm = wid & 1, wn = wid >> 1;       // 2x2 warps, 64x64 each
    const int m0 = blockIdx.y*128, n0 = blockIdx.x*128;
    const int kbeg = blockIdx.z * kchunk;

    auto load_stage = [&](int s, int c){
        int kv = kbeg + c*32;
        int ka = (kv >= TA) ? kv - TA : kv;
        int kb = (kv >= TB) ? kv - TB : kv;
        uint32_t ab = sbase + s*STG_SZ;
        uint32_t bb = ab + STG_A;
        #pragma unroll
        for (int i = tid; i < 512; i += 128){      // A: 128 rows x 32 k
            int row = i >> 2, seg = i & 3;
            int gr = m0 + row;
            const void* src = A + (size_t)(gr < M ? gr : M-1)*lda + ka + seg*8;
            cpa16(ab + (uint32_t)(row*80 + seg*16), src, gr < M);
        }
        #pragma unroll
        for (int i = tid; i < 512; i += 128){      // B: 32 k x 128 n
            int row = i >> 4, seg = i & 15;
            const void* src = Bm + (size_t)(kb + row)*NW_ + n0 + seg*8;
            cpa16(bb + (uint32_t)(row*272 + seg*16), src, true);
        }
    };

    float acc[4][8][4] = {};

    #pragma unroll
    for (int s = 0; s < 3; s++){
        load_stage(s, s);
        asm volatile("cp.async.commit_group;");
    }

    const int lrow = lane & 15, lhi = lane >> 4;
    for (int c = 0; c < nchunks; ++c){
        int s = c & 3;
        asm volatile("cp.async.wait_group 2;");
        __syncthreads();
        uint32_t ab = sbase + s*STG_SZ;
        uint32_t bb = ab + STG_A;
        #pragma unroll
        for (int kk = 0; kk < 2; ++kk){
            int k0 = kk*16;
            unsigned a[4][4], b[8][2];
            #pragma unroll
            for (int mi = 0; mi < 4; ++mi){
                unsigned addr = ab + (uint32_t)((wm*64 + mi*16 + lrow)*80 + (k0 + lhi*8)*2);
                ldsm4(addr, a[mi][0], a[mi][1], a[mi][2], a[mi][3]);
            }
            #pragma unroll
            for (int nt = 0; nt < 4; ++nt){
                unsigned addr = bb + (uint32_t)((k0 + lrow)*272 + (wn*64 + nt*16 + lhi*8)*2);
                unsigned r0,r1,r2,r3;
                ldsm4t(addr, r0,r1,r2,r3);
                b[nt*2  ][0]=r0; b[nt*2  ][1]=r1;
                b[nt*2+1][0]=r2; b[nt*2+1][1]=r3;
            }
            #pragma unroll
            for (int mi = 0; mi < 4; ++mi)
                #pragma unroll
                for (int ni = 0; ni < 8; ++ni)
                    mma16816(acc[mi][ni], a[mi], b[ni]);
        }
        if (c + 3 < nchunks) load_stage((c+3)&3, c+3);
        asm volatile("cp.async.commit_group;");
    }

    // epilogue
    int g = lane >> 2, tig = lane & 3;
    #pragma unroll
    for (int mi = 0; mi < 4; ++mi){
        #pragma unroll
        for (int half = 0; half < 2; ++half){
            int row = m0 + wm*64 + mi*16 + g + half*8;
            if (row >= M) continue;
            float bqv = 0.f, mv0 = 0.f, mv1 = 0.f;
            if constexpr (EPI == 0){
                bqv = bq[row];
                // batch depends on column block; precompute both masks
                mv0 = mask[row];        // b=0
                mv1 = mask[N_ + row];   // b=1
            }
            #pragma unroll
            for (int ni = 0; ni < 8; ++ni){
                int col = n0 + wn*64 + ni*8 + tig*2;
                int bb2 = col >= 384;
                int f = col - bb2*384;
                float v0 = acc[mi][ni][half*2+0];
                float v1 = acc[mi][ni][half*2+1];
                if constexpr (EPI == 0){
                    float mv = bb2 ? mv1 : mv0;
                    v0 += bqv*g_uvw[2*F_+f]   + mv*g_uvw[f]   + g_uvw[F_+f];
                    v1 += bqv*g_uvw[2*F_+f+1] + mv*g_uvw[f+1] + g_uvw[F_+f+1];
                    *(float2*)&g_xp[((size_t)bb2*N_ + row)*F_ + f] = make_float2(v0, v1);
                } else {
                    float* dst = &g_tmp[((size_t)bb2*S_ + row)*F_ + f];
                    atomicAdd(&dst[0], v0);
                    atomicAdd(&dst[1], v1);
                }
            }
        }
    }
}

// ---------------- attention scalars ----------------
__global__ void k_attn(const float* __restrict__ att_src, const float* __restrict__ att_dst){
    int gw = (blockIdx.x*blockDim.x + threadIdx.x) >> 5;
    if (gw >= BN_*H_) return;
    int lane = threadIdx.x & 31;
    int n = gw / H_, h = gw % H_;
    const float* xrow = g_xp + (size_t)n*F_ + h*C_;
    float s1 = 0.f, s2 = 0.f;
    #pragma unroll
    for (int k = 0; k < 4; k++){
        int c = lane + k*32;
        float xv = xrow[c];
        s1 = fmaf(xv, att_src[h*C_ + c], s1);
        s2 = fmaf(xv, att_dst[h*C_ + c], s2);
    }
    #pragma unroll
    for (int o = 16; o; o >>= 1){
        s1 += __shfl_xor_sync(0xffffffffu, s1, o);
        s2 += __shfl_xor_sync(0xffffffffu, s2, o);
    }
    if (lane == 0){ g_asrc[n*H_+h] = s1; g_adst[n*H_+h] = s2; }
}

// ---------------- CSR ----------------
__global__ void k_count(const int* __restrict__ ei){
    int e = blockIdx.x*blockDim.x + threadIdx.x;
    if (e >= BE_) return;
    int b = e / E_, j = e - b*E_;
    atomicAdd(&g_cnt[ei[E_ + j] + b*N_], 1);
}
__global__ void k_scan(){
    __shared__ int ssum[1024];
    int tid = threadIdx.x;
    const int CH = (BN_ + 1023)/1024;
    int base = tid*CH, s = 0;
    for (int i = 0; i < CH; i++){ int idx = base+i; if (idx < BN_) s += g_cnt[idx]; }
    ssum[tid] = s;
    __syncthreads();
    for (int off = 1; off < 1024; off <<= 1){
        int v = (tid >= off) ? ssum[tid-off] : 0;
        __syncthreads();
        ssum[tid] += v;
        __syncthreads();
    }
    int run = ssum[tid] - s;
    for (int i = 0; i < CH; i++){
        int idx = base+i;
        if (idx < BN_){ g_off[idx] = run; run += g_cnt[idx]; }
    }
    if (tid == 1023) g_off[BN_] = ssum[1023];
}
__global__ void k_scatter(const int* __restrict__ ei){
    int e = blockIdx.x*blockDim.x + threadIdx.x;
    if (e >= BE_) return;
    int b = e / E_, j = e - b*E_;
    int src = ei[j] + b*N_;
    int dst = ei[E_ + j] + b*N_;
    int pos = g_off[dst] + atomicAdd(&g_cur[dst], 1);
    g_esrc[pos] = src;
    g_edst[pos] = dst;
}

// ---------------- softmax stats ----------------
__global__ void k_softmax(){
    int gw = (blockIdx.x*blockDim.x + threadIdx.x) >> 5;
    if (gw >= BN_) return;
    int lane = threadIdx.x & 31, n = gw;
    float ad0=g_adst[n*3+0], ad1=g_adst[n*3+1], ad2=g_adst[n*3+2];
    float e0s=lrelu(g_asrc[n*3+0]+ad0), e1s=lrelu(g_asrc[n*3+1]+ad1), e2s=lrelu(g_asrc[n*3+2]+ad2);
    float m0=e0s, m1=e1s, m2=e2s;
    int beg=g_off[n], end=g_off[n+1];
    for (int i = beg+lane; i < end; i += 32){
        int s = g_esrc[i];
        m0 = fmaxf(m0, lrelu(g_asrc[s*3+0]+ad0));
        m1 = fmaxf(m1, lrelu(g_asrc[s*3+1]+ad1));
        m2 = fmaxf(m2, lrelu(g_asrc[s*3+2]+ad2));
    }
    #pragma unroll
    for (int o = 16; o; o >>= 1){
        m0 = fmaxf(m0, __shfl_xor_sync(0xffffffffu, m0, o));
        m1 = fmaxf(m1, __shfl_xor_sync(0xffffffffu, m1, o));
        m2 = fmaxf(m2, __shfl_xor_sync(0xffffffffu, m2, o));
    }
    float s0=0.f, s1=0.f, s2=0.f;
    for (int i = beg+lane; i < end; i += 32){
        int s = g_esrc[i];
        s0 += __expf(lrelu(g_asrc[s*3+0]+ad0) - m0);
        s1 += __expf(lrelu(g_asrc[s*3+1]+ad1) - m1);
        s2 += __expf(lrelu(g_asrc[s*3+2]+ad2) - m2);
    }
    #pragma unroll
    for (int o = 16; o; o >>= 1){
        s0 += __shfl_xor_sync(0xffffffffu, s0, o);
        s1 += __shfl_xor_sync(0xffffffffu, s1, o);
        s2 += __shfl_xor_sync(0xffffffffu, s2, o);
    }
    if (lane == 0){
        s0 += __expf(e0s-m0); s1 += __expf(e1s-m1); s2 += __expf(e2s-m2);
        g_max[n*3+0]=m0; g_max[n*3+1]=m1; g_max[n*3+2]=m2;
        g_rden[n*3+0]=1.f/s0; g_rden[n*3+1]=1.f/s1; g_rden[n*3+2]=1.f/s2;
    }
}
__global__ void k_alpha(){
    int i = blockIdx.x*blockDim.x + threadIdx.x;
    if (i >= BE_) return;
    int s = g_esrc[i], d = g_edst[i];
    #pragma unroll
    for (int h = 0; h < 3; h++){
        float e = lrelu(g_asrc[s*3+h] + g_adst[d*3+h]);
        g_alpha[(size_t)i*3+h] = __expf(e - g_max[d*3+h]) * g_rden[d*3+h];
    }
}

// ---------------- aggregation: block per node, writes hi/lo K-stacked bf16 ----------
__global__ void k_aggregate(const float* __restrict__ bias_gat){
    int n = blockIdx.x;
    int tid = threadIdx.x;      // 0..95
    int h = tid >> 5;
    int beg = g_off[n], end = g_off[n+1];
    const float4* xp4 = (const float4*)g_xp;
    float4 acc = make_float4(0.f,0.f,0.f,0.f);
    for (int i = beg; i < end; i++){
        int s = g_esrc[i];
        float al = g_alpha[(size_t)i*3 + h];
        float4 v = xp4[(size_t)s*96 + tid];
        acc.x = fmaf(v.x, al, acc.x); acc.y = fmaf(v.y, al, acc.y);
        acc.z = fmaf(v.z, al, acc.z); acc.w = fmaf(v.w, al, acc.w);
    }
    float es  = lrelu(g_asrc[n*3+h] + g_adst[n*3+h]);
    float als = __expf(es - g_max[n*3+h]) * g_rden[n*3+h];
    float4 v = xp4[(size_t)n*96 + tid];
    acc.x = fmaf(v.x, als, acc.x); acc.y = fmaf(v.y, als, acc.y);
    acc.z = fmaf(v.z, als, acc.z); acc.w = fmaf(v.w, als, acc.w);
    float4 bg = ((const float4*)bias_gat)[tid];
    acc.x += bg.x; acc.y += bg.y; acc.z += bg.z; acc.w += bg.w;

    int b = n / N_;
    int k = n - b*N_;
    int col = b*384 + tid*4;
    float rv[4] = {acc.x, acc.y, acc.z, acc.w};
    union { __nv_bfloat16 bv[4]; uint2 u; } hh, ll;
    #pragma unroll
    for (int j = 0; j < 4; j++){
        __nv_bfloat16 hb = __float2bfloat16(rv[j]);
        hh.bv[j] = hb;
        ll.bv[j] = __float2bfloat16(rv[j] - __bfloat162float(hb));
    }
    *(uint2*)&g_gat2[(size_t)k*NW_ + col]             = hh.u;
    *(uint2*)&g_gat2[(size_t)(20000 + k)*NW_ + col]   = ll.u;
}

// ---------------- host ----------------
extern "C" void kernel_launch(void* const* d_in, const int* in_sizes, int n_in,
                              void* d_out, int out_size){
    const float* x_enc    = (const float*)d_in[0];
    const float* mask     = (const float*)d_in[1];
    const int*   ei       = (const int*)  d_in[2];
    const float* Wq       = (const float*)d_in[3];
    const float* bq       = (const float*)d_in[4];
    const float* Wm       = (const float*)d_in[5];
    const float* bm       = (const float*)d_in[6];
    const float* Wlin     = (const float*)d_in[7];
    const float* att_src  = (const float*)d_in[8];
    const float* att_dst  = (const float*)d_in[9];
    const float* bias_gat = (const float*)d_in[10];
    const float* Wproj    = (const float*)d_in[11];
    const float* bproj    = (const float*)d_in[12];
    const float* Wtemp    = (const float*)d_in[13];
    const float* btemp    = (const float*)d_in[14];
    float* out = (float*)d_out;

    void *pY2=0, *pWq2=0, *pWp2=0, *pG2=0, *pTmp=0;
    cudaGetSymbolAddress(&pY2,  g_Y2);
    cudaGetSymbolAddress(&pWq2, g_Wq2);
    cudaGetSymbolAddress(&pWp2, g_Wp2);
    cudaGetSymbolAddress(&pG2,  g_gat2);
    cudaGetSymbolAddress(&pTmp, g_tmp);

    cudaFuncSetAttribute(k_mma<0>, cudaFuncAttributeMaxDynamicSharedMemorySize, SMEM_MMA);
    cudaFuncSetAttribute(k_mma<1>, cudaFuncAttributeMaxDynamicSharedMemorySize, SMEM_MMA);

    // 1) uvw
    k_uvw<<<3, 128>>>(Wlin, Wm, bm);
    // 2) Y = x_enc @ Wlin^T, fused hi/lo split into Y2
    k_gemm_bt<<<dim3(F_/64, S_/64, B_), 256>>>(
        x_enc, S_*D_, Wlin, nullptr, 0, D_, F_, nullptr, (__nv_bfloat16*)pY2);
    // 3) Wq split
    k_split_wq2<<<(N_*(S_/4) + 255)/256, 256>>>(Wq);
    // 4) xp GEMM (this is the launch ncu captures)
    k_mma<0><<<dim3(NW_/128, (N_ + 127)/128, 1), 128, SMEM_MMA>>>(
        (const __nv_bfloat16*)pWq2, 1024, N_, 1024,
        (const __nv_bfloat16*)pY2, 512,
        KV_XP, NCH_XP, bq, mask);

    // CSR build
    k_zero<<<(BN_ + 255)/256, 256>>>();
    k_count<<<(BE_ + 255)/256, 256>>>(ei);
    k_scan<<<1, 1024>>>();
    k_scatter<<<(BE_ + 255)/256, 256>>>(ei);

    // attention
    k_attn<<<(BN_*H_*32 + 127)/128, 128>>>(att_src, att_dst);
    k_softmax<<<(BN_*32 + 127)/128, 128>>>();
    k_alpha<<<(BE_ + 255)/256, 256>>>();
    k_aggregate<<<BN_, 96>>>(bias_gat);

    // proj GEMM
    k_split_wp2<<<(S_*(N_/4) + 255)/256, 256>>>(Wproj);
    k_tmpinit<<<(B_*S_*F_ + 255)/256, 256>>>(bproj);
    k_mma<1><<<dim3(NW_/128, S_/128, NSPLIT_PJ), 128, SMEM_MMA>>>(
        (const __nv_bfloat16*)pWp2, 40000, S_, 40000,
        (const __nv_bfloat16*)pG2, 20000,
        KCHUNK_PJ, NCH_PJ, nullptr, nullptr);

    // final out
    k_gemm_bt<<<dim3(DG_/64, (B_*S_)/64, 1), 256>>>(
        (const float*)pTmp, 0, Wtemp, out, 0, F_, DG_, btemp, nullptr);
}

// round 6
// speedup vs baseline: 2.1325x; 1.0113x over previous
#include <cuda_runtime.h>
#include <cuda_bf16.h>
#include <math.h>
#include <stdint.h>

#define B_  2
#define S_  512
#define N_  20000
#define D_  384
#define H_  3
#define C_  128
#define F_  384
#define E_  320000
#define DG_ 128
#define BN_ (B_*N_)
#define BE_ (B_*E_)

#define NW_      768
#define KV_XP    1536
#define NCH_XP   48
#define KV_PJ    60000
#define NSPLIT_PJ 25
#define KCHUNK_PJ 2400
#define NCH_PJ   75
#define STG_A    10240                // 128*40*2
#define STG_B    8704                 // 32*136*2
#define STG_SZ   (STG_A+STG_B)
#define SMEM_MMA (4*STG_SZ)           // 75776

// ---------------- device scratch ----------------
__device__ __align__(16) __nv_bfloat16 g_Y2[1024*NW_];
__device__ __align__(16) __nv_bfloat16 g_Wq2[(size_t)N_*1024];
__device__ __align__(16) __nv_bfloat16 g_Wp2[(size_t)S_*40000];
__device__ __align__(16) __nv_bfloat16 g_gat2[(size_t)40000*NW_];
__device__ float g_uvw[3*F_];
__device__ float g_xp[(size_t)BN_*F_];
__device__ float g_asrc[BN_*H_];
__device__ float g_adst[BN_*H_];
__device__ float g_max[BN_*H_];
__device__ float g_rden[BN_*H_];
__device__ int   g_off[BN_+1];
__device__ int   g_cnt[BN_];
__device__ int   g_cur[BN_];
__device__ int   g_esrc[BE_];
__device__ int   g_edst[BE_];
__device__ float g_alpha[(size_t)BE_*H_];
__device__ float g_tmp[B_*S_*F_];

__device__ __forceinline__ float lrelu(float x){ return x > 0.f ? x : 0.2f*x; }
__device__ __forceinline__ unsigned su(const void* p){
    return (unsigned)__cvta_generic_to_shared(p);
}
__device__ __forceinline__ void cpa16(unsigned dst, const void* src, bool pred){
    int sz = pred ? 16 : 0;
    asm volatile("cp.async.cg.shared.global [%0], [%1], 16, %2;\n"
                 :: "r"(dst), "l"(src), "r"(sz));
}
__device__ __forceinline__ void ldsm4(unsigned addr, unsigned &r0, unsigned &r1, unsigned &r2, unsigned &r3){
    asm volatile("ldmatrix.sync.aligned.m8n8.x4.shared.b16 {%0,%1,%2,%3}, [%4];\n"
                 : "=r"(r0),"=r"(r1),"=r"(r2),"=r"(r3) : "r"(addr));
}
__device__ __forceinline__ void ldsm4t(unsigned addr, unsigned &r0, unsigned &r1, unsigned &r2, unsigned &r3){
    asm volatile("ldmatrix.sync.aligned.m8n8.x4.trans.shared.b16 {%0,%1,%2,%3}, [%4];\n"
                 : "=r"(r0),"=r"(r1),"=r"(r2),"=r"(r3) : "r"(addr));
}
__device__ __forceinline__ void mma16816(float* c, const unsigned* a, const unsigned* b){
    asm volatile("mma.sync.aligned.m16n8k16.row.col.f32.bf16.bf16.f32 "
                 "{%0,%1,%2,%3},{%4,%5,%6,%7},{%8,%9},{%0,%1,%2,%3};\n"
                 : "+f"(c[0]),"+f"(c[1]),"+f"(c[2]),"+f"(c[3])
                 : "r"(a[0]),"r"(a[1]),"r"(a[2]),"r"(a[3]),"r"(b[0]),"r"(b[1]));
}

// ---------------- small kernels ----------------
__global__ void k_zero(){
    int i = blockIdx.x*blockDim.x + threadIdx.x;
    if (i < BN_){ g_cnt[i] = 0; g_cur[i] = 0; }
}
__global__ void k_uvw(const float* __restrict__ Wlin, const float* __restrict__ Wm,
                      const float* __restrict__ bm){
    int f = blockIdx.x*blockDim.x + threadIdx.x;
    if (f >= F_) return;
    float u=0.f, v=0.f, w=0.f;
    for (int d = 0; d < D_; d++){
        float wl = Wlin[f*D_ + d];
        u += wl*Wm[d]; v += wl*bm[d]; w += wl;
    }
    g_uvw[f]=u; g_uvw[F_+f]=v; g_uvw[2*F_+f]=w;
}
__global__ void k_tmpinit(const float* __restrict__ bproj){
    int i = blockIdx.x*blockDim.x + threadIdx.x;
    if (i >= B_*S_*F_) return;
    g_tmp[i] = bproj[(i / F_) % S_];
}

// ---------------- vectorized hi/lo weight splits ----------------
__global__ void k_split_wq2(const float* __restrict__ Wq){
    int i4 = blockIdx.x*blockDim.x + threadIdx.x;
    if (i4 >= N_*(S_/4)) return;
    int m = i4 >> 7, k = (i4 & 127) << 2;
    float4 x = *(const float4*)(Wq + (size_t)m*S_ + k);
    float xs[4] = {x.x, x.y, x.z, x.w};
    union { __nv_bfloat16 b[4]; uint2 u; } hh, ll;
    #pragma unroll
    for (int j = 0; j < 4; j++){
        __nv_bfloat16 h = __float2bfloat16(xs[j]);
        hh.b[j] = h;
        ll.b[j] = __float2bfloat16(xs[j] - __bfloat162float(h));
    }
    size_t base = (size_t)m*1024;
    *(uint2*)&g_Wq2[base + k]       = hh.u;
    *(uint2*)&g_Wq2[base + 512 + k] = ll.u;
}
__global__ void k_split_wp2(const float* __restrict__ Wproj){
    int i4 = blockIdx.x*blockDim.x + threadIdx.x;
    if (i4 >= S_*(N_/4)) return;
    int m = i4 / 5000, k = (i4 % 5000) << 2;
    float4 x = *(const float4*)(Wproj + (size_t)m*N_ + k);
    float xs[4] = {x.x, x.y, x.z, x.w};
    union { __nv_bfloat16 b[4]; uint2 u; } hh, ll;
    #pragma unroll
    for (int j = 0; j < 4; j++){
        __nv_bfloat16 h = __float2bfloat16(xs[j]);
        hh.b[j] = h;
        ll.b[j] = __float2bfloat16(xs[j] - __bfloat162float(h));
    }
    size_t base = (size_t)m*40000;
    *(uint2*)&g_Wp2[base + k]         = hh.u;
    *(uint2*)&g_Wp2[base + 20000 + k] = ll.u;
}

// ---------------- fp32 tiled GEMM (small), C = A @ Bm^T ----------------
__global__ void k_gemm_bt(const float* __restrict__ A, int strideA,
                          const float* __restrict__ Bm,
                          float* __restrict__ C, int strideC,
                          int K, int Ncol, const float* __restrict__ bias_col,
                          __nv_bfloat16* __restrict__ Ysplit){
    const float* Ab = A + blockIdx.z * strideA;
    int m0 = blockIdx.y*64, n0 = blockIdx.x*64;
    __shared__ float As[16][64];
    __shared__ float Bs[16][64];
    int tid = threadIdx.x;
    int tm = tid >> 4, tn = tid & 15;
    int lrow = tid >> 2, lcol = (tid & 3)*4;
    float acc[4][4] = {};
    for (int k0 = 0; k0 < K; k0 += 16){
        float4 av = *(const float4*)(Ab + (m0+lrow)*K + k0 + lcol);
        As[lcol+0][lrow]=av.x; As[lcol+1][lrow]=av.y; As[lcol+2][lrow]=av.z; As[lcol+3][lrow]=av.w;
        float4 bv = *(const float4*)(Bm + (n0+lrow)*K + k0 + lcol);
        Bs[lcol+0][lrow]=bv.x; Bs[lcol+1][lrow]=bv.y; Bs[lcol+2][lrow]=bv.z; Bs[lcol+3][lrow]=bv.w;
        __syncthreads();
        #pragma unroll
        for (int kk = 0; kk < 16; kk++){
            float4 a4 = *(const float4*)&As[kk][tm*4];
            float4 b4 = *(const float4*)&Bs[kk][tn*4];
            float ar[4]={a4.x,a4.y,a4.z,a4.w}, br[4]={b4.x,b4.y,b4.z,b4.w};
            #pragma unroll
            for (int i=0;i<4;i++)
                #pragma unroll
                for (int j=0;j<4;j++) acc[i][j]=fmaf(ar[i],br[j],acc[i][j]);
        }
        __syncthreads();
    }
    #pragma unroll
    for (int i=0;i<4;i++){
        int row = m0 + tm*4 + i;
        #pragma unroll
        for (int j=0;j<4;j++){
            int col = n0 + tn*4 + j;
            float v = acc[i][j];
            if (Ysplit){
                __nv_bfloat16 h = __float2bfloat16(v);
                int gc = blockIdx.z*384 + col;
                Ysplit[(size_t)row*NW_ + gc]         = h;
                Ysplit[(size_t)(512 + row)*NW_ + gc] = __float2bfloat16(v - __bfloat162float(h));
            } else {
                v += bias_col[col];
                (C + blockIdx.z*strideC)[row*Ncol + col] = v;
            }
        }
    }
}

// ---------------- bf16 mma.sync GEMM, 128x128 CTA, 64x64 warps, 4-stage, frag dbuf ----
template<int EPI>
__global__ __launch_bounds__(128, 2)
void k_mma(const __nv_bfloat16* __restrict__ A, int lda, int M, int TA,
           const __nv_bfloat16* __restrict__ Bm, int TB,
           int kchunk, int nchunks,
           const float* __restrict__ bq, const float* __restrict__ mask)
{
    extern __shared__ __align__(16) char smem[];
    uint32_t sbase = su(smem);

    const int tid = threadIdx.x, lane = tid & 31, wid = tid >> 5;
    const int wm = wid & 1, wn = wid >> 1;
    const int m0 = blockIdx.y*128, n0 = blockIdx.x*128;
    const int kbeg = blockIdx.z * kchunk;
    const int lrow = lane & 15, lhi = lane >> 4;

    auto load_stage = [&](int s, int c){
        int kv = kbeg + c*32;
        int ka = (kv >= TA) ? kv - TA : kv;
        int kb = (kv >= TB) ? kv - TB : kv;
        uint32_t ab = sbase + s*STG_SZ;
        uint32_t bb = ab + STG_A;
        #pragma unroll
        for (int i = tid; i < 512; i += 128){
            int row = i >> 2, seg = i & 3;
            int gr = m0 + row;
            const void* src = A + (size_t)(gr < M ? gr : M-1)*lda + ka + seg*8;
            cpa16(ab + (uint32_t)(row*80 + seg*16), src, gr < M);
        }
        #pragma unroll
        for (int i = tid; i < 512; i += 128){
            int row = i >> 4, seg = i & 15;
            const void* src = Bm + (size_t)(kb + row)*NW_ + n0 + seg*8;
            cpa16(bb + (uint32_t)(row*272 + seg*16), src, true);
        }
    };

    unsigned afr[2][4][4], bfr[2][8][2];
    auto ldfr = [&](int s, int kk, int buf){
        uint32_t ab = sbase + s*STG_SZ;
        uint32_t bb = ab + STG_A;
        int k0 = kk*16;
        #pragma unroll
        for (int mi = 0; mi < 4; ++mi){
            unsigned addr = ab + (uint32_t)((wm*64 + mi*16 + lrow)*80 + (k0 + lhi*8)*2);
            ldsm4(addr, afr[buf][mi][0], afr[buf][mi][1], afr[buf][mi][2], afr[buf][mi][3]);
        }
        #pragma unroll
        for (int nt = 0; nt < 4; ++nt){
            unsigned addr = bb + (uint32_t)((k0 + lrow)*272 + (wn*64 + nt*16 + lhi*8)*2);
            unsigned r0,r1,r2,r3;
            ldsm4t(addr, r0,r1,r2,r3);
            bfr[buf][nt*2  ][0]=r0; bfr[buf][nt*2  ][1]=r1;
            bfr[buf][nt*2+1][0]=r2; bfr[buf][nt*2+1][1]=r3;
        }
    };

    float acc[4][8][4] = {};

    #pragma unroll
    for (int s = 0; s < 3; s++){
        load_stage(s, s);
        asm volatile("cp.async.commit_group;");
    }
    asm volatile("cp.async.wait_group 2;");
    __syncthreads();
    ldfr(0, 0, 0);

    for (int c = 0; c < nchunks; ++c){
        int s = c & 3;
        ldfr(s, 1, 1);                          // kk=1 frags (latency hidden by mma below)
        #pragma unroll
        for (int mi = 0; mi < 4; ++mi)
            #pragma unroll
            for (int ni = 0; ni < 8; ++ni)
                mma16816(acc[mi][ni], afr[0][mi], bfr[0][ni]);   // kk=0
        if (c + 3 < nchunks) load_stage((c+3)&3, c+3);
        asm volatile("cp.async.commit_group;");
        if (c + 1 < nchunks){
            asm volatile("cp.async.wait_group 2;");
            __syncthreads();
            ldfr((c+1)&3, 0, 0);                // next chunk kk=0 frags
        }
        #pragma unroll
        for (int mi = 0; mi < 4; ++mi)
            #pragma unroll
            for (int ni = 0; ni < 8; ++ni)
                mma16816(acc[mi][ni], afr[1][mi], bfr[1][ni]);   // kk=1
    }

    // epilogue
    int g = lane >> 2, tig = lane & 3;
    #pragma unroll
    for (int mi = 0; mi < 4; ++mi){
        #pragma unroll
        for (int half = 0; half < 2; ++half){
            int row = m0 + wm*64 + mi*16 + g + half*8;
            if (row >= M) continue;
            float bqv = 0.f, mv0 = 0.f, mv1 = 0.f;
            if constexpr (EPI == 0){
                bqv = bq[row];
                mv0 = mask[row];
                mv1 = mask[N_ + row];
            }
            #pragma unroll
            for (int ni = 0; ni < 8; ++ni){
                int col = n0 + wn*64 + ni*8 + tig*2;
                int bb2 = col >= 384;
                int f = col - bb2*384;
                float v0 = acc[mi][ni][half*2+0];
                float v1 = acc[mi][ni][half*2+1];
                if constexpr (EPI == 0){
                    float mv = bb2 ? mv1 : mv0;
                    v0 += bqv*g_uvw[2*F_+f]   + mv*g_uvw[f]   + g_uvw[F_+f];
                    v1 += bqv*g_uvw[2*F_+f+1] + mv*g_uvw[f+1] + g_uvw[F_+f+1];
                    *(float2*)&g_xp[((size_t)bb2*N_ + row)*F_ + f] = make_float2(v0, v1);
                } else {
                    float* dst = &g_tmp[((size_t)bb2*S_ + row)*F_ + f];
                    atomicAdd(&dst[0], v0);
                    atomicAdd(&dst[1], v1);
                }
            }
        }
    }
}

// ---------------- attention scalars ----------------
__global__ void k_attn(const float* __restrict__ att_src, const float* __restrict__ att_dst){
    int gw = (blockIdx.x*blockDim.x + threadIdx.x) >> 5;
    if (gw >= BN_*H_) return;
    int lane = threadIdx.x & 31;
    int n = gw / H_, h = gw % H_;
    const float* xrow = g_xp + (size_t)n*F_ + h*C_;
    float s1 = 0.f, s2 = 0.f;
    #pragma unroll
    for (int k = 0; k < 4; k++){
        int c = lane + k*32;
        float xv = xrow[c];
        s1 = fmaf(xv, att_src[h*C_ + c], s1);
        s2 = fmaf(xv, att_dst[h*C_ + c], s2);
    }
    #pragma unroll
    for (int o = 16; o; o >>= 1){
        s1 += __shfl_xor_sync(0xffffffffu, s1, o);
        s2 += __shfl_xor_sync(0xffffffffu, s2, o);
    }
    if (lane == 0){ g_asrc[n*H_+h] = s1; g_adst[n*H_+h] = s2; }
}

// ---------------- CSR ----------------
__global__ void k_count(const int* __restrict__ ei){
    int e = blockIdx.x*blockDim.x + threadIdx.x;
    if (e >= BE_) return;
    int b = e / E_, j = e - b*E_;
    atomicAdd(&g_cnt[ei[E_ + j] + b*N_], 1);
}
__global__ void k_scan(){
    __shared__ int ssum[1024];
    int tid = threadIdx.x;
    const int CH = (BN_ + 1023)/1024;
    int base = tid*CH, s = 0;
    for (int i = 0; i < CH; i++){ int idx = base+i; if (idx < BN_) s += g_cnt[idx]; }
    ssum[tid] = s;
    __syncthreads();
    for (int off = 1; off < 1024; off <<= 1){
        int v = (tid >= off) ? ssum[tid-off] : 0;
        __syncthreads();
        ssum[tid] += v;
        __syncthreads();
    }
    int run = ssum[tid] - s;
    for (int i = 0; i < CH; i++){
        int idx = base+i;
        if (idx < BN_){ g_off[idx] = run; run += g_cnt[idx]; }
    }
    if (tid == 1023) g_off[BN_] = ssum[1023];
}
__global__ void k_scatter(const int* __restrict__ ei){
    int e = blockIdx.x*blockDim.x + threadIdx.x;
    if (e >= BE_) return;
    int b = e / E_, j = e - b*E_;
    int src = ei[j] + b*N_;
    int dst = ei[E_ + j] + b*N_;
    int pos = g_off[dst] + atomicAdd(&g_cur[dst], 1);
    g_esrc[pos] = src;
    g_edst[pos] = dst;
}

// ---------------- softmax stats ----------------
__global__ void k_softmax(){
    int gw = (blockIdx.x*blockDim.x + threadIdx.x) >> 5;
    if (gw >= BN_) return;
    int lane = threadIdx.x & 31, n = gw;
    float ad0=g_adst[n*3+0], ad1=g_adst[n*3+1], ad2=g_adst[n*3+2];
    float e0s=lrelu(g_asrc[n*3+0]+ad0), e1s=lrelu(g_asrc[n*3+1]+ad1), e2s=lrelu(g_asrc[n*3+2]+ad2);
    float m0=e0s, m1=e1s, m2=e2s;
    int beg=g_off[n], end=g_off[n+1];
    for (int i = beg+lane; i < end; i += 32){
        int s = g_esrc[i];
        m0 = fmaxf(m0, lrelu(g_asrc[s*3+0]+ad0));
        m1 = fmaxf(m1, lrelu(g_asrc[s*3+1]+ad1));
        m2 = fmaxf(m2, lrelu(g_asrc[s*3+2]+ad2));
    }
    #pragma unroll
    for (int o = 16; o; o >>= 1){
        m0 = fmaxf(m0, __shfl_xor_sync(0xffffffffu, m0, o));
        m1 = fmaxf(m1, __shfl_xor_sync(0xffffffffu, m1, o));
        m2 = fmaxf(m2, __shfl_xor_sync(0xffffffffu, m2, o));
    }
    float s0=0.f, s1=0.f, s2=0.f;
    for (int i = beg+lane; i < end; i += 32){
        int s = g_esrc[i];
        s0 += __expf(lrelu(g_asrc[s*3+0]+ad0) - m0);
        s1 += __expf(lrelu(g_asrc[s*3+1]+ad1) - m1);
        s2 += __expf(lrelu(g_asrc[s*3+2]+ad2) - m2);
    }
    #pragma unroll
    for (int o = 16; o; o >>= 1){
        s0 += __shfl_xor_sync(0xffffffffu, s0, o);
        s1 += __shfl_xor_sync(0xffffffffu, s1, o);
        s2 += __shfl_xor_sync(0xffffffffu, s2, o);
    }
    if (lane == 0){
        s0 += __expf(e0s-m0); s1 += __expf(e1s-m1); s2 += __expf(e2s-m2);
        g_max[n*3+0]=m0; g_max[n*3+1]=m1; g_max[n*3+2]=m2;
        g_rden[n*3+0]=1.f/s0; g_rden[n*3+1]=1.f/s1; g_rden[n*3+2]=1.f/s2;
    }
}
__global__ void k_alpha(){
    int i = blockIdx.x*blockDim.x + threadIdx.x;
    if (i >= BE_) return;
    int s = g_esrc[i], d = g_edst[i];
    #pragma unroll
    for (int h = 0; h < 3; h++){
        float e = lrelu(g_asrc[s*3+h] + g_adst[d*3+h]);
        g_alpha[(size_t)i*3+h] = __expf(e - g_max[d*3+h]) * g_rden[d*3+h];
    }
}

// ---------------- aggregation ----------------
__global__ void k_aggregate(const float* __restrict__ bias_gat){
    int n = blockIdx.x;
    int tid = threadIdx.x;
    int h = tid >> 5;
    int beg = g_off[n], end = g_off[n+1];
    const float4* xp4 = (const float4*)g_xp;
    float4 acc = make_float4(0.f,0.f,0.f,0.f);
    for (int i = beg; i < end; i++){
        int s = g_esrc[i];
        float al = g_alpha[(size_t)i*3 + h];
        float4 v = xp4[(size_t)s*96 + tid];
        acc.x = fmaf(v.x, al, acc.x); acc.y = fmaf(v.y, al, acc.y);
        acc.z = fmaf(v.z, al, acc.z); acc.w = fmaf(v.w, al, acc.w);
    }
    float es  = lrelu(g_asrc[n*3+h] + g_adst[n*3+h]);
    float als = __expf(es - g_max[n*3+h]) * g_rden[n*3+h];
    float4 v = xp4[(size_t)n*96 + tid];
    acc.x = fmaf(v.x, als, acc.x); acc.y = fmaf(v.y, als, acc.y);
    acc.z = fmaf(v.z, als, acc.z); acc.w = fmaf(v.w, als, acc.w);
    float4 bg = ((const float4*)bias_gat)[tid];
    acc.x += bg.x; acc.y += bg.y; acc.z += bg.z; acc.w += bg.w;

    int b = n / N_;
    int k = n - b*N_;
    int col = b*384 + tid*4;
    float rv[4] = {acc.x, acc.y, acc.z, acc.w};
    union { __nv_bfloat16 bv[4]; uint2 u; } hh, ll;
    #pragma unroll
    for (int j = 0; j < 4; j++){
        __nv_bfloat16 hb = __float2bfloat16(rv[j]);
        hh.bv[j] = hb;
        ll.bv[j] = __float2bfloat16(rv[j] - __bfloat162float(hb));
    }
    *(uint2*)&g_gat2[(size_t)k*NW_ + col]             = hh.u;
    *(uint2*)&g_gat2[(size_t)(20000 + k)*NW_ + col]   = ll.u;
}

// ---------------- host ----------------
extern "C" void kernel_launch(void* const* d_in, const int* in_sizes, int n_in,
                              void* d_out, int out_size){
    const float* x_enc    = (const float*)d_in[0];
    const float* mask     = (const float*)d_in[1];
    const int*   ei       = (const int*)  d_in[2];
    const float* Wq       = (const float*)d_in[3];
    const float* bq       = (const float*)d_in[4];
    const float* Wm       = (const float*)d_in[5];
    const float* bm       = (const float*)d_in[6];
    const float* Wlin     = (const float*)d_in[7];
    const float* att_src  = (const float*)d_in[8];
    const float* att_dst  = (const float*)d_in[9];
    const float* bias_gat = (const float*)d_in[10];
    const float* Wproj    = (const float*)d_in[11];
    const float* bproj    = (const float*)d_in[12];
    const float* Wtemp    = (const float*)d_in[13];
    const float* btemp    = (const float*)d_in[14];
    float* out = (float*)d_out;

    void *pY2=0, *pWq2=0, *pWp2=0, *pG2=0, *pTmp=0;
    cudaGetSymbolAddress(&pY2,  g_Y2);
    cudaGetSymbolAddress(&pWq2, g_Wq2);
    cudaGetSymbolAddress(&pWp2, g_Wp2);
    cudaGetSymbolAddress(&pG2,  g_gat2);
    cudaGetSymbolAddress(&pTmp, g_tmp);

    cudaFuncSetAttribute(k_mma<0>, cudaFuncAttributeMaxDynamicSharedMemorySize, SMEM_MMA);
    cudaFuncSetAttribute(k_mma<1>, cudaFuncAttributeMaxDynamicSharedMemorySize, SMEM_MMA);

    k_uvw<<<3, 128>>>(Wlin, Wm, bm);
    k_gemm_bt<<<dim3(F_/64, S_/64, B_), 256>>>(
        x_enc, S_*D_, Wlin, nullptr, 0, D_, F_, nullptr, (__nv_bfloat16*)pY2);
    k_split_wq2<<<(N_*(S_/4) + 255)/256, 256>>>(Wq);
    k_mma<0><<<dim3(NW_/128, (N_ + 127)/128, 1), 128, SMEM_MMA>>>(
        (const __nv_bfloat16*)pWq2, 1024, N_, 1024,
        (const __nv_bfloat16*)pY2, 512,
        KV_XP, NCH_XP, bq, mask);

    k_zero<<<(BN_ + 255)/256, 256>>>();
    k_count<<<(BE_ + 255)/256, 256>>>(ei);
    k_scan<<<1, 1024>>>();
    k_scatter<<<(BE_ + 255)/256, 256>>>(ei);

    k_attn<<<(BN_*H_*32 + 127)/128, 128>>>(att_src, att_dst);
    k_softmax<<<(BN_*32 + 127)/128, 128>>>();
    k_alpha<<<(BE_ + 255)/256, 256>>>();
    k_aggregate<<<BN_, 96>>>(bias_gat);

    k_split_wp2<<<(S_*(N_/4) + 255)/256, 256>>>(Wproj);
    k_tmpinit<<<(B_*S_*F_ + 255)/256, 256>>>(bproj);
    k_mma<1><<<dim3(NW_/128, S_/128, NSPLIT_PJ), 128, SMEM_MMA>>>(
        (const __nv_bfloat16*)pWp2, 40000, S_, 40000,
        (const __nv_bfloat16*)pG2, 20000,
        KCHUNK_PJ, NCH_PJ, nullptr, nullptr);

    k_gemm_bt<<<dim3(DG_/64, (B_*S_)/64, 1), 256>>>(
        (const float*)pTmp, 0, Wtemp, out, 0, F_, DG_, btemp, nullptr);
}